// round 2
// baseline (speedup 1.0000x reference)
#include <cuda_runtime.h>
#include <math.h>

#define BB 4
#define CIN 256
#define PP 64
#define HH 128
#define WW 128
#define HWSZ (HH*WW)
#define KK 8
#define BN_EPS 1e-5f

// Scratch (device globals: allocation-free)
__device__ float g_h[BB*PP*HWSZ];      // after 1x1 conv + BN + SiLU
__device__ float g_mind[BB*HWSZ];      // per-pixel min distance / (tau+1e-6)
__device__ float g_factor[BB*HWSZ];    // 1 + gamma*attn
__device__ unsigned int g_minbits[BB];
__device__ unsigned int g_maxbits[BB];

__device__ __forceinline__ float sigmoidf_(float x){ return 1.0f/(1.0f+__expf(-x)); }
__device__ __forceinline__ float siluf_(float x){ return x*sigmoidf_(x); }

__device__ __forceinline__ unsigned long long ffma2(unsigned long long a,
                                                    unsigned long long b,
                                                    unsigned long long c){
    unsigned long long d;
    asm("fma.rn.f32x2 %0, %1, %2, %3;" : "=l"(d) : "l"(a), "l"(b), "l"(c));
    return d;
}

// ---------------------------------------------------------------- init
__global__ void k_init(){
    int t = threadIdx.x;
    if (t < BB){ g_minbits[t] = 0x7F7FFFFFu; g_maxbits[t] = 0u; }
}

// ---------------------------------------------------------------- k1: 1x1 conv (GEMM 64x16384x256) + BN + SiLU, packed f32x2 FMA
__global__ __launch_bounds__(256) void k1_gemm(const float* __restrict__ x,
                                               const float* __restrict__ w,
                                               const float* __restrict__ bn){
    __shared__ float ws[32][128];       // [k][cout duplicated pairs]
    __shared__ float xs[32][128];       // [k][pixel]
    int b    = blockIdx.y;
    int pix0 = blockIdx.x * 128;
    int tid  = threadIdx.x;
    const float* xb = x + (size_t)b*CIN*HWSZ;

    unsigned long long acc[4][4];       // [cout][pixel-pair], f32x2
    #pragma unroll
    for (int i=0;i<4;i++)
        #pragma unroll
        for (int j=0;j<4;j++) acc[i][j] = 0ull;

    int ty = tid >> 4, tx = tid & 15;   // 16x16 thread grid: 4 couts x 8 pixels each

    for (int k0 = 0; k0 < CIN; k0 += 32){
        // load W chunk, duplicated: ws[kk][2c] = ws[kk][2c+1] = w[c][k]
        #pragma unroll
        for (int i=0;i<8;i++){
            int idx  = tid + i*256;       // 0..2047
            int cout = idx & 63;
            int kk   = idx >> 6;          // 0..31
            float v  = w[cout*CIN + k0 + kk];
            *(float2*)&ws[kk][cout*2] = make_float2(v, v);
        }
        // load X chunk as float4 (coalesced)
        #pragma unroll
        for (int i=0;i<4;i++){
            int idx = tid + i*256;        // 0..1023
            int kk  = idx >> 5;           // 0..31
            int p4  = idx & 31;           // 0..31
            *(float4*)&xs[kk][p4*4] = *(const float4*)&xb[(size_t)(k0+kk)*HWSZ + pix0 + p4*4];
        }
        __syncthreads();
        #pragma unroll
        for (int kk=0; kk<32; kk++){
            unsigned long long av[4];
            #pragma unroll
            for (int i=0;i<4;i++)
                av[i] = *(const unsigned long long*)&ws[kk][(ty*4+i)*2];
            ulonglong2 blo = *(const ulonglong2*)&xs[kk][tx*8];
            ulonglong2 bhi = *(const ulonglong2*)&xs[kk][tx*8+4];
            unsigned long long bv[4] = {blo.x, blo.y, bhi.x, bhi.y};
            #pragma unroll
            for (int i=0;i<4;i++)
                #pragma unroll
                for (int j=0;j<4;j++)
                    acc[i][j] = ffma2(av[i], bv[j], acc[i][j]);
        }
        __syncthreads();
    }
    // epilogue: BN (folded affine) + SiLU
    #pragma unroll
    for (int i=0;i<4;i++){
        int c = ty*4 + i;
        float g  = bn[c], be = bn[PP+c], m = bn[2*PP+c], v = bn[3*PP+c];
        float sc = g * rsqrtf(v + BN_EPS);
        float sh = be - m*sc;
        float o[8];
        #pragma unroll
        for (int j=0;j<4;j++){
            float lo, hi;
            asm("mov.b64 {%0,%1}, %2;" : "=f"(lo), "=f"(hi) : "l"(acc[i][j]));
            o[2*j]   = siluf_(fmaf(lo, sc, sh));
            o[2*j+1] = siluf_(fmaf(hi, sc, sh));
        }
        float* hp = g_h + (size_t)b*PP*HWSZ + (size_t)c*HWSZ + pix0 + tx*8;
        *(float4*)hp     = make_float4(o[0],o[1],o[2],o[3]);
        *(float4*)(hp+4) = make_float4(o[4],o[5],o[6],o[7]);
    }
}

// ---------------------------------------------------------------- k23: fused dw3x3+BN+SiLU -> min proto distance -> per-image min/max
__global__ __launch_bounds__(256) void k23_dwdist(const float* __restrict__ dw,
                                                  const float* __restrict__ bn,
                                                  const float* __restrict__ protos){
    __shared__ float tile[32][10][34];   // 32 channels x (8+2) x (32+2) halo tile
    __shared__ float ps[KK][PP];
    __shared__ float pn[KK];
    __shared__ float sdw[PP][9];
    __shared__ float ssc[PP], ssh[PP];
    __shared__ float smin[8], smax[8];

    int b   = blockIdx.z;
    int gx0 = blockIdx.x*32, gy0 = blockIdx.y*8;
    int tx  = threadIdx.x,  ty  = threadIdx.y;
    int tid = ty*32 + tx;

    for (int i = tid; i < KK*PP; i += 256) ps[i>>6][i&63] = protos[i];
    for (int i = tid; i < PP*9;  i += 256) sdw[i/9][i%9] = dw[i];
    if (tid < PP){
        float g=bn[tid], be=bn[PP+tid], m=bn[2*PP+tid], v=bn[3*PP+tid];
        float sc = g*rsqrtf(v+BN_EPS);
        ssc[tid] = sc; ssh[tid] = be - m*sc;
    }
    if (tid < KK){
        float s = 0.f;
        #pragma unroll
        for (int c=0;c<PP;c++){ float p = protos[tid*PP+c]; s = fmaf(p,p,s); }
        pn[tid] = s;
    }

    const float* hb = g_h + (size_t)b*PP*HWSZ;
    float nf = 0.f, dot[KK];
    #pragma unroll
    for (int k=0;k<KK;k++) dot[k] = 0.f;

    for (int c0 = 0; c0 < PP; c0 += 32){
        __syncthreads();
        // load 32-channel halo tile (rows of 34 contiguous floats)
        for (int i = tid; i < 32*340; i += 256){
            int c   = i / 340;
            int rem = i - c*340;
            int r   = rem / 34;
            int col = rem - r*34;
            int yy = gy0 - 1 + r, xx = gx0 - 1 + col;
            float v = 0.f;
            if ((unsigned)yy < HH && (unsigned)xx < WW)
                v = hb[(size_t)(c0+c)*HWSZ + yy*WW + xx];
            tile[c][r][col] = v;
        }
        __syncthreads();
        #pragma unroll 4
        for (int c = 0; c < 32; c++){
            int cc = c0 + c;
            float s = 0.f;
            #pragma unroll
            for (int dy=0;dy<3;dy++)
                #pragma unroll
                for (int dx=0;dx<3;dx++)
                    s = fmaf(sdw[cc][dy*3+dx], tile[c][ty+dy][tx+dx], s);
            float pr = siluf_(fmaf(s, ssc[cc], ssh[cc]));
            nf = fmaf(pr, pr, nf);
            #pragma unroll
            for (int k=0;k<KK;k++) dot[k] = fmaf(pr, ps[k][cc], dot[k]);
        }
    }

    float m = 3.4e38f;
    #pragma unroll
    for (int k=0;k<KK;k++) m = fminf(m, nf + pn[k] - 2.f*dot[k]);
    float md = sqrtf(fmaxf(m, 0.f)) * (1.0f/(1.0f + 1e-6f));
    g_mind[b*HWSZ + (gy0+ty)*WW + gx0+tx] = md;

    // block reduce min/max then atomics (values >= 0 -> uint ordering valid)
    float wmin = md, wmax = md;
    #pragma unroll
    for (int o=16;o>0;o>>=1){
        wmin = fminf(wmin, __shfl_xor_sync(0xffffffffu, wmin, o));
        wmax = fmaxf(wmax, __shfl_xor_sync(0xffffffffu, wmax, o));
    }
    int wid = tid >> 5, lid = tid & 31;
    if (lid == 0){ smin[wid] = wmin; smax[wid] = wmax; }
    __syncthreads();
    if (tid == 0){
        float bm = smin[0], bM = smax[0];
        #pragma unroll
        for (int i=1;i<8;i++){ bm = fminf(bm, smin[i]); bM = fmaxf(bM, smax[i]); }
        atomicMin(&g_minbits[b], __float_as_uint(bm));
        atomicMax(&g_maxbits[b], __float_as_uint(bM));
    }
}

// ---------------------------------------------------------------- k4: deviation -> two DS-conv branches -> fuse -> sigmoid -> factor
__global__ __launch_bounds__(256) void k4_attn(
        const float* __restrict__ bs_dw, const float* __restrict__ bs_bn1,
        const float* __restrict__ bs_pw, const float* __restrict__ bs_bn2,
        const float* __restrict__ bl_dw, const float* __restrict__ bl_bn1,
        const float* __restrict__ bl_pw, const float* __restrict__ bl_bn2,
        const float* __restrict__ fuse_w, const float* __restrict__ fuse_b,
        const float* __restrict__ gamma){
    __shared__ float sdev[12][36];       // 8x32 tile + 2-halo for 5x5
    int b   = blockIdx.z;
    int gx0 = blockIdx.x*32, gy0 = blockIdx.y*8;
    int tx  = threadIdx.x,  ty  = threadIdx.y;
    int tid = ty*32 + tx;

    float dmin = __uint_as_float(g_minbits[b]);
    float dmax = __uint_as_float(g_maxbits[b]);
    float inv  = 1.0f/(dmax - dmin + 1e-6f);
    const float* mdp = g_mind + b*HWSZ;

    for (int i = tid; i < 12*36; i += 256){
        int ly = i/36, lx = i%36;
        int yy = gy0 - 2 + ly, xx = gx0 - 2 + lx;
        float v = 0.f;                    // zero padding (conv semantics)
        if ((unsigned)yy < HH && (unsigned)xx < WW)
            v = (mdp[yy*WW + xx] - dmin) * inv;
        sdev[ly][lx] = v;
    }
    __syncthreads();

    int cy = ty + 2, cx = tx + 2;
    float t1 = 0.f;
    #pragma unroll
    for (int dy=0;dy<3;dy++)
        #pragma unroll
        for (int dx=0;dx<3;dx++)
            t1 = fmaf(bs_dw[dy*3+dx], sdev[cy+dy-1][cx+dx-1], t1);
    { float g=bs_bn1[0], be=bs_bn1[1], m=bs_bn1[2], v=bs_bn1[3];
      float sc = g*rsqrtf(v+BN_EPS); t1 = siluf_(fmaf(t1, sc, be - m*sc)); }
    float t2 = 0.f;
    #pragma unroll
    for (int dy=0;dy<5;dy++)
        #pragma unroll
        for (int dx=0;dx<5;dx++)
            t2 = fmaf(bl_dw[dy*5+dx], sdev[cy+dy-2][cx+dx-2], t2);
    { float g=bl_bn1[0], be=bl_bn1[1], m=bl_bn1[2], v=bl_bn1[3];
      float sc = g*rsqrtf(v+BN_EPS); t2 = siluf_(fmaf(t2, sc, be - m*sc)); }

    float logit = fuse_b[0];
    #pragma unroll
    for (int c=0;c<8;c++){
        float g=bs_bn2[c], be=bs_bn2[8+c], m=bs_bn2[16+c], v=bs_bn2[24+c];
        float sc = g*rsqrtf(v+BN_EPS);
        float f1 = siluf_(fmaf(bs_pw[c]*t1, sc, be - m*sc));
        logit = fmaf(fuse_w[c], f1, logit);
    }
    #pragma unroll
    for (int c=0;c<8;c++){
        float g=bl_bn2[c], be=bl_bn2[8+c], m=bl_bn2[16+c], v=bl_bn2[24+c];
        float sc = g*rsqrtf(v+BN_EPS);
        float f2 = siluf_(fmaf(bl_pw[c]*t2, sc, be - m*sc));
        logit = fmaf(fuse_w[8+c], f2, logit);
    }
    int gy = gy0 + ty, gx = gx0 + tx;
    g_factor[b*HWSZ + gy*WW + gx] = 1.0f + gamma[0]*sigmoidf_(logit);
}

// ---------------------------------------------------------------- k5: out = x * factor (broadcast over channels), pure streaming
__global__ __launch_bounds__(256) void k5_apply(const float* __restrict__ x,
                                                float* __restrict__ out){
    size_t i = ((size_t)blockIdx.x*256 + threadIdx.x) * 4;
    float4 xv = *(const float4*)(x + i);
    size_t pos = i & (size_t)(HWSZ - 1);
    int b      = (int)(i >> 22);
    float4 fv = *(const float4*)(g_factor + (size_t)b*HWSZ + pos);
    float4 ov;
    ov.x = xv.x * fv.x;
    ov.y = xv.y * fv.y;
    ov.z = xv.z * fv.z;
    ov.w = xv.w * fv.w;
    *(float4*)(out + i) = ov;
}

// ---------------------------------------------------------------- launch
extern "C" void kernel_launch(void* const* d_in, const int* in_sizes, int n_in,
                              void* d_out, int out_size){
    const float* x      = (const float*)d_in[0];
    const float* fp_w1  = (const float*)d_in[1];
    const float* fp_bn1 = (const float*)d_in[2];
    const float* fp_dw  = (const float*)d_in[3];
    const float* fp_bn2 = (const float*)d_in[4];
    const float* protos = (const float*)d_in[5];
    const float* bs_dw  = (const float*)d_in[6];
    const float* bs_bn1 = (const float*)d_in[7];
    const float* bs_pw  = (const float*)d_in[8];
    const float* bs_bn2 = (const float*)d_in[9];
    const float* bl_dw  = (const float*)d_in[10];
    const float* bl_bn1 = (const float*)d_in[11];
    const float* bl_pw  = (const float*)d_in[12];
    const float* bl_bn2 = (const float*)d_in[13];
    const float* fuse_w = (const float*)d_in[14];
    const float* fuse_b = (const float*)d_in[15];
    const float* gamma  = (const float*)d_in[16];
    float* out = (float*)d_out;

    k_init<<<1, 32>>>();
    k1_gemm<<<dim3(128, BB), 256>>>(x, fp_w1, fp_bn1);
    k23_dwdist<<<dim3(4, 16, BB), dim3(32, 8)>>>(fp_dw, fp_bn2, protos);
    k4_attn<<<dim3(4, 16, BB), dim3(32, 8)>>>(bs_dw, bs_bn1, bs_pw, bs_bn2,
                                              bl_dw, bl_bn1, bl_pw, bl_bn2,
                                              fuse_w, fuse_b, gamma);
    k5_apply<<<(BB*CIN*HWSZ)/4/256, 256>>>(x, out);
}

// round 3
// speedup vs baseline: 2.1359x; 2.1359x over previous
#include <cuda_runtime.h>
#include <math.h>

#define BB 4
#define CIN 256
#define PP 64
#define HH 128
#define WW 128
#define HWSZ (HH*WW)
#define KK 8
#define BN_EPS 1e-5f

// Scratch (device globals: allocation-free)
__device__ float g_h[BB*PP*HWSZ];      // after 1x1 conv + BN + SiLU
__device__ float g_mind[BB*HWSZ];      // per-pixel min distance / (tau+1e-6)
__device__ float g_factor[BB*HWSZ];    // 1 + gamma*attn
__device__ unsigned int g_minbits[BB];
__device__ unsigned int g_maxbits[BB];

__device__ __forceinline__ float sigmoidf_(float x){ return 1.0f/(1.0f+__expf(-x)); }
__device__ __forceinline__ float siluf_(float x){ return x*sigmoidf_(x); }

// ---------------------------------------------------------------- init
__global__ void k_init(){
    int t = threadIdx.x;
    if (t < BB){ g_minbits[t] = 0x7F7FFFFFu; g_maxbits[t] = 0u; }
}

// ---------------------------------------------------------------- k1: 1x1 conv (GEMM 64x16384x256) + BN + SiLU
// 64 couts x 256 pixels per block, 8x8 register tile, double-buffered smem.
__global__ __launch_bounds__(256, 2) void k1_gemm(const float* __restrict__ x,
                                                  const float* __restrict__ w,
                                                  const float* __restrict__ bn){
    __shared__ float ws[2][16][68];     // [buf][k][cout] (padded to 68 vs bank conflicts)
    __shared__ float xs[2][16][256];    // [buf][k][pixel]
    int b    = blockIdx.y;
    int pix0 = blockIdx.x * 256;
    int tid  = threadIdx.x;
    int ty   = tid >> 5;                // 0..7  -> cout group (8 couts)
    int tx   = tid & 31;                // 0..31 -> pixel group (8 pixels)
    const float* xb = x + (size_t)b*CIN*HWSZ + pix0;

    float acc[8][8];
    #pragma unroll
    for (int i=0;i<8;i++)
        #pragma unroll
        for (int j=0;j<8;j++) acc[i][j] = 0.f;

    // staging assignment: thread -> (cout, 4 consecutive k) for W
    int wcout = tid >> 2;               // 0..63
    int wkq   = (tid & 3) * 4;          // 0,4,8,12

    float4 wreg;
    float4 xreg[4];

    // prologue: load chunk 0
    wreg = *(const float4*)&w[wcout*CIN + wkq];
    #pragma unroll
    for (int i=0;i<4;i++){
        int idx = tid + i*256;          // 0..1023 float4-slots
        int kk  = idx >> 6;             // 0..15
        int p4  = idx & 63;             // 0..63
        xreg[i] = *(const float4*)&xb[(size_t)kk*HWSZ + p4*4];
    }
    ws[0][wkq+0][wcout] = wreg.x;
    ws[0][wkq+1][wcout] = wreg.y;
    ws[0][wkq+2][wcout] = wreg.z;
    ws[0][wkq+3][wcout] = wreg.w;
    #pragma unroll
    for (int i=0;i<4;i++){
        int idx = tid + i*256;
        *(float4*)&xs[0][idx>>6][(idx&63)*4] = xreg[i];
    }
    __syncthreads();

    #pragma unroll 1
    for (int c = 0; c < 16; c++){
        int cur = c & 1;
        // prefetch next chunk into registers (overlaps with compute below)
        if (c + 1 < 16){
            int k0 = (c+1)*16;
            wreg = *(const float4*)&w[wcout*CIN + k0 + wkq];
            #pragma unroll
            for (int i=0;i<4;i++){
                int idx = tid + i*256;
                int kk  = idx >> 6;
                int p4  = idx & 63;
                xreg[i] = *(const float4*)&xb[(size_t)(k0+kk)*HWSZ + p4*4];
            }
        }
        // compute on current buffer
        #pragma unroll
        for (int kk=0; kk<16; kk++){
            float av[8], bv[8];
            *(float4*)(av)   = *(const float4*)&ws[cur][kk][ty*8];
            *(float4*)(av+4) = *(const float4*)&ws[cur][kk][ty*8+4];
            *(float4*)(bv)   = *(const float4*)&xs[cur][kk][tx*8];
            *(float4*)(bv+4) = *(const float4*)&xs[cur][kk][tx*8+4];
            #pragma unroll
            for (int i=0;i<8;i++)
                #pragma unroll
                for (int j=0;j<8;j++)
                    acc[i][j] = fmaf(av[i], bv[j], acc[i][j]);
        }
        // commit staged chunk
        if (c + 1 < 16){
            int nxt = cur ^ 1;
            ws[nxt][wkq+0][wcout] = wreg.x;
            ws[nxt][wkq+1][wcout] = wreg.y;
            ws[nxt][wkq+2][wcout] = wreg.z;
            ws[nxt][wkq+3][wcout] = wreg.w;
            #pragma unroll
            for (int i=0;i<4;i++){
                int idx = tid + i*256;
                *(float4*)&xs[nxt][idx>>6][(idx&63)*4] = xreg[i];
            }
        }
        __syncthreads();
    }

    // epilogue: BN (folded affine) + SiLU, store
    #pragma unroll
    for (int i=0;i<8;i++){
        int cc = ty*8 + i;
        float g  = bn[cc], be = bn[PP+cc], m = bn[2*PP+cc], v = bn[3*PP+cc];
        float sc = g * rsqrtf(v + BN_EPS);
        float sh = be - m*sc;
        float o[8];
        #pragma unroll
        for (int j=0;j<8;j++) o[j] = siluf_(fmaf(acc[i][j], sc, sh));
        float* hp = g_h + (size_t)b*PP*HWSZ + (size_t)cc*HWSZ + pix0 + tx*8;
        *(float4*)hp     = make_float4(o[0],o[1],o[2],o[3]);
        *(float4*)(hp+4) = make_float4(o[4],o[5],o[6],o[7]);
    }
}

// ---------------------------------------------------------------- k23: fused dw3x3+BN+SiLU -> min proto distance -> per-image min/max
__global__ __launch_bounds__(256) void k23_dwdist(const float* __restrict__ dw,
                                                  const float* __restrict__ bn,
                                                  const float* __restrict__ protos){
    __shared__ float tile[32][10][34];   // 32 channels x (8+2) x (32+2) halo tile
    __shared__ float ps[KK][PP];
    __shared__ float pn[KK];
    __shared__ float sdw[PP][9];
    __shared__ float ssc[PP], ssh[PP];
    __shared__ float smin[8], smax[8];

    int b   = blockIdx.z;
    int gx0 = blockIdx.x*32, gy0 = blockIdx.y*8;
    int tx  = threadIdx.x,  ty  = threadIdx.y;
    int tid = ty*32 + tx;

    for (int i = tid; i < KK*PP; i += 256) ps[i>>6][i&63] = protos[i];
    for (int i = tid; i < PP*9;  i += 256) sdw[i/9][i%9] = dw[i];
    if (tid < PP){
        float g=bn[tid], be=bn[PP+tid], m=bn[2*PP+tid], v=bn[3*PP+tid];
        float sc = g*rsqrtf(v+BN_EPS);
        ssc[tid] = sc; ssh[tid] = be - m*sc;
    }
    if (tid < KK){
        float s = 0.f;
        #pragma unroll
        for (int c=0;c<PP;c++){ float p = protos[tid*PP+c]; s = fmaf(p,p,s); }
        pn[tid] = s;
    }

    const float* hb = g_h + (size_t)b*PP*HWSZ;
    float nf = 0.f, dot[KK];
    #pragma unroll
    for (int k=0;k<KK;k++) dot[k] = 0.f;

    for (int c0 = 0; c0 < PP; c0 += 32){
        __syncthreads();
        // load 32-channel halo tile (rows of 34 contiguous floats)
        for (int i = tid; i < 32*340; i += 256){
            int c   = i / 340;
            int rem = i - c*340;
            int r   = rem / 34;
            int col = rem - r*34;
            int yy = gy0 - 1 + r, xx = gx0 - 1 + col;
            float v = 0.f;
            if ((unsigned)yy < HH && (unsigned)xx < WW)
                v = hb[(size_t)(c0+c)*HWSZ + yy*WW + xx];
            tile[c][r][col] = v;
        }
        __syncthreads();
        #pragma unroll 4
        for (int c = 0; c < 32; c++){
            int cc = c0 + c;
            float s = 0.f;
            #pragma unroll
            for (int dy=0;dy<3;dy++)
                #pragma unroll
                for (int dx=0;dx<3;dx++)
                    s = fmaf(sdw[cc][dy*3+dx], tile[c][ty+dy][tx+dx], s);
            float pr = siluf_(fmaf(s, ssc[cc], ssh[cc]));
            nf = fmaf(pr, pr, nf);
            #pragma unroll
            for (int k=0;k<KK;k++) dot[k] = fmaf(pr, ps[k][cc], dot[k]);
        }
    }

    float m = 3.4e38f;
    #pragma unroll
    for (int k=0;k<KK;k++) m = fminf(m, nf + pn[k] - 2.f*dot[k]);
    float md = sqrtf(fmaxf(m, 0.f)) * (1.0f/(1.0f + 1e-6f));
    g_mind[b*HWSZ + (gy0+ty)*WW + gx0+tx] = md;

    // block reduce min/max then atomics (values >= 0 -> uint ordering valid)
    float wmin = md, wmax = md;
    #pragma unroll
    for (int o=16;o>0;o>>=1){
        wmin = fminf(wmin, __shfl_xor_sync(0xffffffffu, wmin, o));
        wmax = fmaxf(wmax, __shfl_xor_sync(0xffffffffu, wmax, o));
    }
    int wid = tid >> 5, lid = tid & 31;
    if (lid == 0){ smin[wid] = wmin; smax[wid] = wmax; }
    __syncthreads();
    if (tid == 0){
        float bm = smin[0], bM = smax[0];
        #pragma unroll
        for (int i=1;i<8;i++){ bm = fminf(bm, smin[i]); bM = fmaxf(bM, smax[i]); }
        atomicMin(&g_minbits[b], __float_as_uint(bm));
        atomicMax(&g_maxbits[b], __float_as_uint(bM));
    }
}

// ---------------------------------------------------------------- k4: deviation -> two DS-conv branches -> fuse -> sigmoid -> factor
__global__ __launch_bounds__(256) void k4_attn(
        const float* __restrict__ bs_dw, const float* __restrict__ bs_bn1,
        const float* __restrict__ bs_pw, const float* __restrict__ bs_bn2,
        const float* __restrict__ bl_dw, const float* __restrict__ bl_bn1,
        const float* __restrict__ bl_pw, const float* __restrict__ bl_bn2,
        const float* __restrict__ fuse_w, const float* __restrict__ fuse_b,
        const float* __restrict__ gamma){
    __shared__ float sdev[12][36];       // 8x32 tile + 2-halo for 5x5
    int b   = blockIdx.z;
    int gx0 = blockIdx.x*32, gy0 = blockIdx.y*8;
    int tx  = threadIdx.x,  ty  = threadIdx.y;
    int tid = ty*32 + tx;

    float dmin = __uint_as_float(g_minbits[b]);
    float dmax = __uint_as_float(g_maxbits[b]);
    float inv  = 1.0f/(dmax - dmin + 1e-6f);
    const float* mdp = g_mind + b*HWSZ;

    for (int i = tid; i < 12*36; i += 256){
        int ly = i/36, lx = i%36;
        int yy = gy0 - 2 + ly, xx = gx0 - 2 + lx;
        float v = 0.f;                    // zero padding (conv semantics)
        if ((unsigned)yy < HH && (unsigned)xx < WW)
            v = (mdp[yy*WW + xx] - dmin) * inv;
        sdev[ly][lx] = v;
    }
    __syncthreads();

    int cy = ty + 2, cx = tx + 2;
    float t1 = 0.f;
    #pragma unroll
    for (int dy=0;dy<3;dy++)
        #pragma unroll
        for (int dx=0;dx<3;dx++)
            t1 = fmaf(bs_dw[dy*3+dx], sdev[cy+dy-1][cx+dx-1], t1);
    { float g=bs_bn1[0], be=bs_bn1[1], m=bs_bn1[2], v=bs_bn1[3];
      float sc = g*rsqrtf(v+BN_EPS); t1 = siluf_(fmaf(t1, sc, be - m*sc)); }
    float t2 = 0.f;
    #pragma unroll
    for (int dy=0;dy<5;dy++)
        #pragma unroll
        for (int dx=0;dx<5;dx++)
            t2 = fmaf(bl_dw[dy*5+dx], sdev[cy+dy-2][cx+dx-2], t2);
    { float g=bl_bn1[0], be=bl_bn1[1], m=bl_bn1[2], v=bl_bn1[3];
      float sc = g*rsqrtf(v+BN_EPS); t2 = siluf_(fmaf(t2, sc, be - m*sc)); }

    float logit = fuse_b[0];
    #pragma unroll
    for (int c=0;c<8;c++){
        float g=bs_bn2[c], be=bs_bn2[8+c], m=bs_bn2[16+c], v=bs_bn2[24+c];
        float sc = g*rsqrtf(v+BN_EPS);
        float f1 = siluf_(fmaf(bs_pw[c]*t1, sc, be - m*sc));
        logit = fmaf(fuse_w[c], f1, logit);
    }
    #pragma unroll
    for (int c=0;c<8;c++){
        float g=bl_bn2[c], be=bl_bn2[8+c], m=bl_bn2[16+c], v=bl_bn2[24+c];
        float sc = g*rsqrtf(v+BN_EPS);
        float f2 = siluf_(fmaf(bl_pw[c]*t2, sc, be - m*sc));
        logit = fmaf(fuse_w[8+c], f2, logit);
    }
    int gy = gy0 + ty, gx = gx0 + tx;
    g_factor[b*HWSZ + gy*WW + gx] = 1.0f + gamma[0]*sigmoidf_(logit);
}

// ---------------------------------------------------------------- k5: out = x * factor (broadcast over channels), pure streaming
__global__ __launch_bounds__(256) void k5_apply(const float* __restrict__ x,
                                                float* __restrict__ out){
    size_t i = ((size_t)blockIdx.x*256 + threadIdx.x) * 4;
    float4 xv = *(const float4*)(x + i);
    size_t pos = i & (size_t)(HWSZ - 1);
    int b      = (int)(i >> 22);
    float4 fv = *(const float4*)(g_factor + (size_t)b*HWSZ + pos);
    float4 ov;
    ov.x = xv.x * fv.x;
    ov.y = xv.y * fv.y;
    ov.z = xv.z * fv.z;
    ov.w = xv.w * fv.w;
    *(float4*)(out + i) = ov;
}

// ---------------------------------------------------------------- launch
extern "C" void kernel_launch(void* const* d_in, const int* in_sizes, int n_in,
                              void* d_out, int out_size){
    const float* x      = (const float*)d_in[0];
    const float* fp_w1  = (const float*)d_in[1];
    const float* fp_bn1 = (const float*)d_in[2];
    const float* fp_dw  = (const float*)d_in[3];
    const float* fp_bn2 = (const float*)d_in[4];
    const float* protos = (const float*)d_in[5];
    const float* bs_dw  = (const float*)d_in[6];
    const float* bs_bn1 = (const float*)d_in[7];
    const float* bs_pw  = (const float*)d_in[8];
    const float* bs_bn2 = (const float*)d_in[9];
    const float* bl_dw  = (const float*)d_in[10];
    const float* bl_bn1 = (const float*)d_in[11];
    const float* bl_pw  = (const float*)d_in[12];
    const float* bl_bn2 = (const float*)d_in[13];
    const float* fuse_w = (const float*)d_in[14];
    const float* fuse_b = (const float*)d_in[15];
    const float* gamma  = (const float*)d_in[16];
    float* out = (float*)d_out;

    k_init<<<1, 32>>>();
    k1_gemm<<<dim3(64, BB), 256>>>(x, fp_w1, fp_bn1);
    k23_dwdist<<<dim3(4, 16, BB), dim3(32, 8)>>>(fp_dw, fp_bn2, protos);
    k4_attn<<<dim3(4, 16, BB), dim3(32, 8)>>>(bs_dw, bs_bn1, bs_pw, bs_bn2,
                                              bl_dw, bl_bn1, bl_pw, bl_bn2,
                                              fuse_w, fuse_b, gamma);
    k5_apply<<<(BB*CIN*HWSZ)/4/256, 256>>>(x, out);
}

// round 4
// speedup vs baseline: 2.1515x; 1.0073x over previous
#include <cuda_runtime.h>
#include <math.h>

#define BB 4
#define CIN 256
#define PP 64
#define HH 128
#define WW 128
#define HWSZ (HH*WW)
#define KK 8
#define BN_EPS 1e-5f

// Scratch (device globals: allocation-free)
__device__ float g_h[BB*PP*HWSZ];      // after 1x1 conv + BN + SiLU
__device__ float g_mind[BB*HWSZ];      // per-pixel min distance / (tau+1e-6)
__device__ float g_factor[BB*HWSZ];    // 1 + gamma*attn
__device__ unsigned int g_minbits[BB];
__device__ unsigned int g_maxbits[BB];

__device__ __forceinline__ float sigmoidf_(float x){ return 1.0f/(1.0f+__expf(-x)); }
__device__ __forceinline__ float siluf_(float x){ return x*sigmoidf_(x); }

__device__ __forceinline__ unsigned int f2tf32(float x){
    unsigned int r;
    asm("cvt.rna.tf32.f32 %0, %1;" : "=r"(r) : "f"(x));
    return r;
}
// split x into tf32 hi + tf32 lo (hi + lo ~ x to ~2^-22)
__device__ __forceinline__ void tf32split(float x, unsigned int& hi, unsigned int& lo){
    hi = f2tf32(x);
    float l = x - __uint_as_float(hi);
    lo = f2tf32(l);
}
__device__ __forceinline__ void mma_tf32(float* d, const unsigned int* a,
                                         unsigned int b0, unsigned int b1){
    asm volatile("mma.sync.aligned.m16n8k8.row.col.f32.tf32.tf32.f32 "
                 "{%0,%1,%2,%3}, {%4,%5,%6,%7}, {%8,%9}, {%0,%1,%2,%3};"
                 : "+f"(d[0]), "+f"(d[1]), "+f"(d[2]), "+f"(d[3])
                 : "r"(a[0]), "r"(a[1]), "r"(a[2]), "r"(a[3]), "r"(b0), "r"(b1));
}

// ---------------------------------------------------------------- k1: 1x1 conv (GEMM per batch: C[16384,64] = X^T[16384,256] W^T[256,64])
// tensor cores, tf32 3x compensation. Block: 128 pixels x 64 couts, 8 warps.
__global__ __launch_bounds__(256, 2) void k1_mma(const float* __restrict__ x,
                                                 const float* __restrict__ w,
                                                 const float* __restrict__ bn){
    __shared__ float xs[16][136];    // [k][pixel] (pad: stride%32 = 8)
    __shared__ float ws[16][72];     // [k][cout]  (pad: stride%32 = 8)
    __shared__ float ssc[PP], ssh[PP];

    int b    = blockIdx.y;
    int pix0 = blockIdx.x * 128;
    int tid  = threadIdx.x;
    int wrp  = tid >> 5;
    int lane = tid & 31;
    int gid  = lane >> 2;           // 0..7
    int tig  = lane & 3;            // 0..3
    int pw   = wrp * 16;            // warp's local pixel base
    const float* xb = x + (size_t)b*CIN*HWSZ + pix0;

    // fold init of global min/max (runs before k23)
    if (blockIdx.x == 0 && blockIdx.y == 0 && tid < BB){
        g_minbits[tid] = 0x7F7FFFFFu; g_maxbits[tid] = 0u;
    }
    // BN affine precompute
    if (tid < PP){
        float g = bn[tid], be = bn[PP+tid], m = bn[2*PP+tid], v = bn[3*PP+tid];
        float sc = g * rsqrtf(v + BN_EPS);
        ssc[tid] = sc; ssh[tid] = be - m*sc;
    }

    float acc[8][4];
    #pragma unroll
    for (int j=0;j<8;j++)
        #pragma unroll
        for (int i=0;i<4;i++) acc[j][i] = 0.f;

    // staging indices
    int xkk0 = tid >> 5;            // for i-th quarter: kk = (tid + i*256)>>5
    int wcout = tid >> 2;           // 0..63
    int wkq   = (tid & 3) * 4;      // 0,4,8,12

    float4 xr[2], wr;

    // prologue: chunk 0
    #pragma unroll
    for (int i=0;i<2;i++){
        int idx = tid + i*256;
        xr[i] = *(const float4*)&xb[(size_t)(idx>>5)*HWSZ + (idx&31)*4];
    }
    wr = *(const float4*)&w[wcout*CIN + wkq];
    #pragma unroll
    for (int i=0;i<2;i++){
        int idx = tid + i*256;
        *(float4*)&xs[idx>>5][(idx&31)*4] = xr[i];
    }
    ws[wkq+0][wcout] = wr.x;
    ws[wkq+1][wcout] = wr.y;
    ws[wkq+2][wcout] = wr.z;
    ws[wkq+3][wcout] = wr.w;
    __syncthreads();

    #pragma unroll 1
    for (int c = 0; c < 16; c++){
        // prefetch next chunk
        if (c + 1 < 16){
            int k0 = (c+1)*16;
            #pragma unroll
            for (int i=0;i<2;i++){
                int idx = tid + i*256;
                xr[i] = *(const float4*)&xb[(size_t)(k0 + (idx>>5))*HWSZ + (idx&31)*4];
            }
            wr = *(const float4*)&w[wcout*CIN + k0 + wkq];
        }
        // compute: two k8 steps on this chunk
        #pragma unroll
        for (int ks = 0; ks < 2; ks++){
            int kb = ks*8;
            // A fragment (pixels x k), from xs
            float ao[4];
            ao[0] = xs[kb+tig  ][pw+gid  ];
            ao[1] = xs[kb+tig  ][pw+gid+8];
            ao[2] = xs[kb+tig+4][pw+gid  ];
            ao[3] = xs[kb+tig+4][pw+gid+8];
            unsigned int ah[4], al[4];
            #pragma unroll
            for (int i=0;i<4;i++) tf32split(ao[i], ah[i], al[i]);
            // B fragments per n-tile (couts)
            #pragma unroll
            for (int j=0;j<8;j++){
                float bo0 = ws[kb+tig  ][j*8+gid];
                float bo1 = ws[kb+tig+4][j*8+gid];
                unsigned int bh0, bl0, bh1, bl1;
                tf32split(bo0, bh0, bl0);
                tf32split(bo1, bh1, bl1);
                mma_tf32(acc[j], ah, bh0, bh1);   // hi*hi
                mma_tf32(acc[j], al, bh0, bh1);   // lo*hi
                mma_tf32(acc[j], ah, bl0, bl1);   // hi*lo
            }
        }
        __syncthreads();
        if (c + 1 < 16){
            #pragma unroll
            for (int i=0;i<2;i++){
                int idx = tid + i*256;
                *(float4*)&xs[idx>>5][(idx&31)*4] = xr[i];
            }
            ws[wkq+0][wcout] = wr.x;
            ws[wkq+1][wcout] = wr.y;
            ws[wkq+2][wcout] = wr.z;
            ws[wkq+3][wcout] = wr.w;
        }
        __syncthreads();
    }

    // epilogue: BN + SiLU, scatter store (8-lane 32B sectors)
    int px = pix0 + pw + gid;
    #pragma unroll
    for (int j=0;j<8;j++){
        int c0 = j*8 + tig*2;
        float sc0 = ssc[c0],   sh0 = ssh[c0];
        float sc1 = ssc[c0+1], sh1 = ssh[c0+1];
        float* h0 = g_h + ((size_t)(b*PP + c0  ))*HWSZ;
        float* h1 = g_h + ((size_t)(b*PP + c0+1))*HWSZ;
        h0[px]   = siluf_(fmaf(acc[j][0], sc0, sh0));
        h1[px]   = siluf_(fmaf(acc[j][1], sc1, sh1));
        h0[px+8] = siluf_(fmaf(acc[j][2], sc0, sh0));
        h1[px+8] = siluf_(fmaf(acc[j][3], sc1, sh1));
    }
}

// ---------------------------------------------------------------- k23: fused dw3x3+BN+SiLU -> min proto distance -> per-image min/max
__global__ __launch_bounds__(256) void k23_dwdist(const float* __restrict__ dw,
                                                  const float* __restrict__ bn,
                                                  const float* __restrict__ protos){
    __shared__ float tile[32][10][34];
    __shared__ float ps[KK][PP];
    __shared__ float pn[KK];
    __shared__ float sdw[PP][9];
    __shared__ float ssc[PP], ssh[PP];
    __shared__ float smin[8], smax[8];

    int b   = blockIdx.z;
    int gx0 = blockIdx.x*32, gy0 = blockIdx.y*8;
    int tx  = threadIdx.x,  ty  = threadIdx.y;
    int tid = ty*32 + tx;

    for (int i = tid; i < KK*PP; i += 256) ps[i>>6][i&63] = protos[i];
    for (int i = tid; i < PP*9;  i += 256) sdw[i/9][i%9] = dw[i];
    if (tid < PP){
        float g=bn[tid], be=bn[PP+tid], m=bn[2*PP+tid], v=bn[3*PP+tid];
        float sc = g*rsqrtf(v+BN_EPS);
        ssc[tid] = sc; ssh[tid] = be - m*sc;
    }
    if (tid < KK){
        float s = 0.f;
        #pragma unroll
        for (int c=0;c<PP;c++){ float p = protos[tid*PP+c]; s = fmaf(p,p,s); }
        pn[tid] = s;
    }

    const float* hb = g_h + (size_t)b*PP*HWSZ;
    float nf = 0.f, dot[KK];
    #pragma unroll
    for (int k=0;k<KK;k++) dot[k] = 0.f;

    for (int c0 = 0; c0 < PP; c0 += 32){
        __syncthreads();
        for (int i = tid; i < 32*340; i += 256){
            int c   = i / 340;
            int rem = i - c*340;
            int r   = rem / 34;
            int col = rem - r*34;
            int yy = gy0 - 1 + r, xx = gx0 - 1 + col;
            float v = 0.f;
            if ((unsigned)yy < HH && (unsigned)xx < WW)
                v = hb[(size_t)(c0+c)*HWSZ + yy*WW + xx];
            tile[c][r][col] = v;
        }
        __syncthreads();
        #pragma unroll 4
        for (int c = 0; c < 32; c++){
            int cc = c0 + c;
            float s = 0.f;
            #pragma unroll
            for (int dy=0;dy<3;dy++)
                #pragma unroll
                for (int dx=0;dx<3;dx++)
                    s = fmaf(sdw[cc][dy*3+dx], tile[c][ty+dy][tx+dx], s);
            float pr = siluf_(fmaf(s, ssc[cc], ssh[cc]));
            nf = fmaf(pr, pr, nf);
            #pragma unroll
            for (int k=0;k<KK;k++) dot[k] = fmaf(pr, ps[k][cc], dot[k]);
        }
    }

    float m = 3.4e38f;
    #pragma unroll
    for (int k=0;k<KK;k++) m = fminf(m, nf + pn[k] - 2.f*dot[k]);
    float md = sqrtf(fmaxf(m, 0.f)) * (1.0f/(1.0f + 1e-6f));
    g_mind[b*HWSZ + (gy0+ty)*WW + gx0+tx] = md;

    float wmin = md, wmax = md;
    #pragma unroll
    for (int o=16;o>0;o>>=1){
        wmin = fminf(wmin, __shfl_xor_sync(0xffffffffu, wmin, o));
        wmax = fmaxf(wmax, __shfl_xor_sync(0xffffffffu, wmax, o));
    }
    int wid = tid >> 5, lid = tid & 31;
    if (lid == 0){ smin[wid] = wmin; smax[wid] = wmax; }
    __syncthreads();
    if (tid == 0){
        float bm = smin[0], bM = smax[0];
        #pragma unroll
        for (int i=1;i<8;i++){ bm = fminf(bm, smin[i]); bM = fmaxf(bM, smax[i]); }
        atomicMin(&g_minbits[b], __float_as_uint(bm));
        atomicMax(&g_maxbits[b], __float_as_uint(bM));
    }
}

// ---------------------------------------------------------------- k4: deviation -> two DS-conv branches -> fuse -> sigmoid -> factor
__global__ __launch_bounds__(256) void k4_attn(
        const float* __restrict__ bs_dw, const float* __restrict__ bs_bn1,
        const float* __restrict__ bs_pw, const float* __restrict__ bs_bn2,
        const float* __restrict__ bl_dw, const float* __restrict__ bl_bn1,
        const float* __restrict__ bl_pw, const float* __restrict__ bl_bn2,
        const float* __restrict__ fuse_w, const float* __restrict__ fuse_b,
        const float* __restrict__ gamma){
    __shared__ float sdev[12][36];
    int b   = blockIdx.z;
    int gx0 = blockIdx.x*32, gy0 = blockIdx.y*8;
    int tx  = threadIdx.x,  ty  = threadIdx.y;
    int tid = ty*32 + tx;

    float dmin = __uint_as_float(g_minbits[b]);
    float dmax = __uint_as_float(g_maxbits[b]);
    float inv  = 1.0f/(dmax - dmin + 1e-6f);
    const float* mdp = g_mind + b*HWSZ;

    for (int i = tid; i < 12*36; i += 256){
        int ly = i/36, lx = i%36;
        int yy = gy0 - 2 + ly, xx = gx0 - 2 + lx;
        float v = 0.f;
        if ((unsigned)yy < HH && (unsigned)xx < WW)
            v = (mdp[yy*WW + xx] - dmin) * inv;
        sdev[ly][lx] = v;
    }
    __syncthreads();

    int cy = ty + 2, cx = tx + 2;
    float t1 = 0.f;
    #pragma unroll
    for (int dy=0;dy<3;dy++)
        #pragma unroll
        for (int dx=0;dx<3;dx++)
            t1 = fmaf(bs_dw[dy*3+dx], sdev[cy+dy-1][cx+dx-1], t1);
    { float g=bs_bn1[0], be=bs_bn1[1], m=bs_bn1[2], v=bs_bn1[3];
      float sc = g*rsqrtf(v+BN_EPS); t1 = siluf_(fmaf(t1, sc, be - m*sc)); }
    float t2 = 0.f;
    #pragma unroll
    for (int dy=0;dy<5;dy++)
        #pragma unroll
        for (int dx=0;dx<5;dx++)
            t2 = fmaf(bl_dw[dy*5+dx], sdev[cy+dy-2][cx+dx-2], t2);
    { float g=bl_bn1[0], be=bl_bn1[1], m=bl_bn1[2], v=bl_bn1[3];
      float sc = g*rsqrtf(v+BN_EPS); t2 = siluf_(fmaf(t2, sc, be - m*sc)); }

    float logit = fuse_b[0];
    #pragma unroll
    for (int c=0;c<8;c++){
        float g=bs_bn2[c], be=bs_bn2[8+c], m=bs_bn2[16+c], v=bs_bn2[24+c];
        float sc = g*rsqrtf(v+BN_EPS);
        float f1 = siluf_(fmaf(bs_pw[c]*t1, sc, be - m*sc));
        logit = fmaf(fuse_w[c], f1, logit);
    }
    #pragma unroll
    for (int c=0;c<8;c++){
        float g=bl_bn2[c], be=bl_bn2[8+c], m=bl_bn2[16+c], v=bl_bn2[24+c];
        float sc = g*rsqrtf(v+BN_EPS);
        float f2 = siluf_(fmaf(bl_pw[c]*t2, sc, be - m*sc));
        logit = fmaf(fuse_w[8+c], f2, logit);
    }
    int gy = gy0 + ty, gx = gx0 + tx;
    g_factor[b*HWSZ + gy*WW + gx] = 1.0f + gamma[0]*sigmoidf_(logit);
}

// ---------------------------------------------------------------- k5: out = x * factor (broadcast over channels), pure streaming
__global__ __launch_bounds__(256) void k5_apply(const float* __restrict__ x,
                                                float* __restrict__ out){
    size_t i = ((size_t)blockIdx.x*256 + threadIdx.x) * 4;
    float4 xv = *(const float4*)(x + i);
    size_t pos = i & (size_t)(HWSZ - 1);
    int b      = (int)(i >> 22);
    float4 fv = *(const float4*)(g_factor + (size_t)b*HWSZ + pos);
    float4 ov;
    ov.x = xv.x * fv.x;
    ov.y = xv.y * fv.y;
    ov.z = xv.z * fv.z;
    ov.w = xv.w * fv.w;
    *(float4*)(out + i) = ov;
}

// ---------------------------------------------------------------- launch
extern "C" void kernel_launch(void* const* d_in, const int* in_sizes, int n_in,
                              void* d_out, int out_size){
    const float* x      = (const float*)d_in[0];
    const float* fp_w1  = (const float*)d_in[1];
    const float* fp_bn1 = (const float*)d_in[2];
    const float* fp_dw  = (const float*)d_in[3];
    const float* fp_bn2 = (const float*)d_in[4];
    const float* protos = (const float*)d_in[5];
    const float* bs_dw  = (const float*)d_in[6];
    const float* bs_bn1 = (const float*)d_in[7];
    const float* bs_pw  = (const float*)d_in[8];
    const float* bs_bn2 = (const float*)d_in[9];
    const float* bl_dw  = (const float*)d_in[10];
    const float* bl_bn1 = (const float*)d_in[11];
    const float* bl_pw  = (const float*)d_in[12];
    const float* bl_bn2 = (const float*)d_in[13];
    const float* fuse_w = (const float*)d_in[14];
    const float* fuse_b = (const float*)d_in[15];
    const float* gamma  = (const float*)d_in[16];
    float* out = (float*)d_out;

    k1_mma<<<dim3(128, BB), 256>>>(x, fp_w1, fp_bn1);
    k23_dwdist<<<dim3(4, 16, BB), dim3(32, 8)>>>(fp_dw, fp_bn2, protos);
    k4_attn<<<dim3(4, 16, BB), dim3(32, 8)>>>(bs_dw, bs_bn1, bs_pw, bs_bn2,
                                              bl_dw, bl_bn1, bl_pw, bl_bn2,
                                              fuse_w, fuse_b, gamma);
    k5_apply<<<(BB*CIN*HWSZ)/4/256, 256>>>(x, out);
}

// round 6
// speedup vs baseline: 2.3813x; 1.1068x over previous
#include <cuda_runtime.h>
#include <cstdint>
#include <math.h>

#define BB 4
#define CIN 256
#define PP 64
#define HH 128
#define WW 128
#define HWSZ (HH*WW)
#define KK 8
#define BN_EPS 1e-5f

// Scratch (device globals: allocation-free)
__device__ float g_h[BB*PP*HWSZ];      // after 1x1 conv + BN + SiLU
__device__ float g_mind[BB*HWSZ];      // per-pixel min distance / (tau+1e-6)
__device__ float g_factor[BB*HWSZ];    // 1 + gamma*attn
__device__ unsigned int g_minbits[BB];
__device__ unsigned int g_maxbits[BB];

__device__ __forceinline__ float sigmoidf_(float x){ return 1.0f/(1.0f+__expf(-x)); }
__device__ __forceinline__ float siluf_(float x){ return x*sigmoidf_(x); }

__device__ __forceinline__ uint32_t smem_u32(const void* p){
    uint32_t a;
    asm("{ .reg .u64 t; cvta.to.shared.u64 t, %1; cvt.u32.u64 %0, t; }" : "=r"(a) : "l"(p));
    return a;
}
// pack two floats -> bf16x2 (low 16 = x0, high 16 = x1)
__device__ __forceinline__ uint32_t pack_bf16x2(float x0, float x1){
    uint32_t r;
    asm("cvt.rn.bf16x2.f32 %0, %1, %2;" : "=r"(r) : "f"(x1), "f"(x0));
    return r;
}
__device__ __forceinline__ void ldsm_x4(uint32_t* r, uint32_t addr){
    asm volatile("ldmatrix.sync.aligned.m8n8.x4.shared.b16 {%0,%1,%2,%3}, [%4];"
        : "=r"(r[0]),"=r"(r[1]),"=r"(r[2]),"=r"(r[3]) : "r"(addr));
}
__device__ __forceinline__ void ldsm_x2(uint32_t& r0, uint32_t& r1, uint32_t addr){
    asm volatile("ldmatrix.sync.aligned.m8n8.x2.shared.b16 {%0,%1}, [%2];"
        : "=r"(r0),"=r"(r1) : "r"(addr));
}
__device__ __forceinline__ void mma_bf16(float* d, const uint32_t* a, uint32_t b0, uint32_t b1){
    asm volatile("mma.sync.aligned.m16n8k16.row.col.f32.bf16.bf16.f32 "
        "{%0,%1,%2,%3},{%4,%5,%6,%7},{%8,%9},{%0,%1,%2,%3};"
        : "+f"(d[0]),"+f"(d[1]),"+f"(d[2]),"+f"(d[3])
        : "r"(a[0]),"r"(a[1]),"r"(a[2]),"r"(a[3]),"r"(b0),"r"(b1));
}

// ---------------- k1 SMEM layout (dynamic, byte offsets) ----------------
#define APITCH 36                        // u32 pitch (144B: 16B-aligned, bank-spread)
#define SM_SC    0                       // ssc[64]
#define SM_SH    256                     // ssh[64]
#define SM_AHI   512                     // 128 x APITCH u32
#define SM_ALO   (SM_AHI + 128*APITCH*4)
#define SM_BHI   (SM_ALO + 128*APITCH*4)
#define SM_BLO   (SM_BHI + 64*APITCH*4)
#define SM_TOTAL (SM_BLO + 64*APITCH*4)  // 55808 B

// ---------------------------------------------------------------- k1: 1x1 conv (GEMM 128pix x 64cout x 256K per CTA)
// bf16 HMMA, 2-term decomposition, split-once-to-SMEM, ldmatrix fragments.
__global__ __launch_bounds__(256)
void k1_mma(const float* __restrict__ x, const float* __restrict__ w,
            const float* __restrict__ bn){
    extern __shared__ char smem[];
    uint32_t sb = smem_u32(smem);
    float* ssc = (float*)(smem + SM_SC);
    float* ssh = (float*)(smem + SM_SH);
    uint32_t* a_hi = (uint32_t*)(smem + SM_AHI);
    uint32_t* a_lo = (uint32_t*)(smem + SM_ALO);
    uint32_t* b_hi = (uint32_t*)(smem + SM_BHI);
    uint32_t* b_lo = (uint32_t*)(smem + SM_BLO);

    int b    = blockIdx.y;
    int pix0 = blockIdx.x * 128;
    int tid  = threadIdx.x;
    int wid  = tid >> 5;
    int lane = tid & 31;
    int gid  = lane >> 2, tig = lane & 3;
    int pw   = (wid >> 1) * 32;          // warp pixel base (M32)
    int n0w  = (wid & 1) * 32;           // warp cout base (N32)
    const float* xb = x + (size_t)b*CIN*HWSZ + pix0;

    if (blockIdx.x == 0 && blockIdx.y == 0 && tid < BB){
        g_minbits[tid] = 0x7F7FFFFFu; g_maxbits[tid] = 0u;
    }
    if (tid < PP){
        float g = bn[tid], be = bn[PP+tid], m = bn[2*PP+tid], v = bn[3*PP+tid];
        float sc = g * rsqrtf(v + BN_EPS);
        ssc[tid] = sc; ssh[tid] = be - m*sc;
    }

    float acc[2][4][4];
    #pragma unroll
    for (int mt=0;mt<2;mt++)
        #pragma unroll
        for (int j=0;j<4;j++)
            #pragma unroll
            for (int i=0;i<4;i++) acc[mt][j][i] = 0.f;

    // ldmatrix source addresses (byte): A x4, B x2
    uint32_t a_row = (uint32_t)(lane & 15);
    uint32_t a_kof = (uint32_t)(lane >> 4) * 16;     // bytes (4 u32)
    uint32_t b_row = (uint32_t)(lane & 7);
    uint32_t b_kof = (uint32_t)((lane >> 3) & 1) * 16;

    #pragma unroll 1
    for (int c = 0; c < 4; c++){
        int k0 = c * 64;
        // ---- convert A: 128 px x 32 kpairs, hi/lo, STS.128 ----
        #pragma unroll
        for (int it = 0; it < 4; it++){
            int i  = tid + it*256;       // 0..1023
            int px = i & 127;
            int kg = i >> 7;             // 0..7 (4 kpairs each)
            const float* xp = xb + px;
            uint32_t hi[4], lo[4];
            #pragma unroll
            for (int t=0;t<4;t++){
                int kp = kg*4 + t;
                float x0 = xp[(size_t)(k0+2*kp  )*HWSZ];
                float x1 = xp[(size_t)(k0+2*kp+1)*HWSZ];
                uint32_t h = pack_bf16x2(x0, x1);
                float h0 = __uint_as_float(h << 16);
                float h1 = __uint_as_float(h & 0xFFFF0000u);
                hi[t] = h;
                lo[t] = pack_bf16x2(x0 - h0, x1 - h1);
            }
            *(uint4*)(a_hi + px*APITCH + kg*4) = make_uint4(hi[0],hi[1],hi[2],hi[3]);
            *(uint4*)(a_lo + px*APITCH + kg*4) = make_uint4(lo[0],lo[1],lo[2],lo[3]);
        }
        // ---- convert B: 64 couts x 32 kpairs ----
        #pragma unroll
        for (int it = 0; it < 2; it++){
            int i  = tid + it*256;       // 0..511
            int co = i >> 3;
            int kg = i & 7;
            const float* wp = w + co*CIN + k0 + kg*8;
            float4 w0 = *(const float4*)wp;
            float4 w1 = *(const float4*)(wp + 4);
            float xv[8] = {w0.x,w0.y,w0.z,w0.w,w1.x,w1.y,w1.z,w1.w};
            uint32_t hi[4], lo[4];
            #pragma unroll
            for (int t=0;t<4;t++){
                uint32_t h = pack_bf16x2(xv[2*t], xv[2*t+1]);
                float h0 = __uint_as_float(h << 16);
                float h1 = __uint_as_float(h & 0xFFFF0000u);
                hi[t] = h;
                lo[t] = pack_bf16x2(xv[2*t] - h0, xv[2*t+1] - h1);
            }
            *(uint4*)(b_hi + co*APITCH + kg*4) = make_uint4(hi[0],hi[1],hi[2],hi[3]);
            *(uint4*)(b_lo + co*APITCH + kg*4) = make_uint4(lo[0],lo[1],lo[2],lo[3]);
        }
        __syncthreads();

        // ---- MMA: 4 k16 steps ----
        #pragma unroll
        for (int ks = 0; ks < 4; ks++){
            uint32_t kbyte = (uint32_t)ks * 32;      // ks*8 u32
            uint32_t ah[2][4], al[2][4];
            #pragma unroll
            for (int mt=0;mt<2;mt++){
                uint32_t ra = (pw + mt*16 + a_row) * (APITCH*4) + kbyte + a_kof;
                ldsm_x4(ah[mt], sb + SM_AHI + ra);
                ldsm_x4(al[mt], sb + SM_ALO + ra);
            }
            #pragma unroll
            for (int j=0;j<4;j++){
                uint32_t rb = (n0w + j*8 + b_row) * (APITCH*4) + kbyte + b_kof;
                uint32_t bh0, bh1, bl0, bl1;
                ldsm_x2(bh0, bh1, sb + SM_BHI + rb);
                ldsm_x2(bl0, bl1, sb + SM_BLO + rb);
                #pragma unroll
                for (int mt=0;mt<2;mt++){
                    mma_bf16(acc[mt][j], ah[mt], bh0, bh1);
                    mma_bf16(acc[mt][j], al[mt], bh0, bh1);
                    mma_bf16(acc[mt][j], ah[mt], bl0, bl1);
                }
            }
        }
        __syncthreads();
    }

    // ---- epilogue: BN + SiLU, store ----
    #pragma unroll
    for (int mt=0;mt<2;mt++){
        int pix = pix0 + pw + mt*16 + gid;
        #pragma unroll
        for (int j=0;j<4;j++){
            int cc = n0w + j*8 + tig*2;
            float sc0 = ssc[cc],   sh0 = ssh[cc];
            float sc1 = ssc[cc+1], sh1 = ssh[cc+1];
            float* h0 = g_h + (size_t)(b*PP + cc)*HWSZ;
            float* h1 = h0 + HWSZ;
            h0[pix]   = siluf_(fmaf(acc[mt][j][0], sc0, sh0));
            h1[pix]   = siluf_(fmaf(acc[mt][j][1], sc1, sh1));
            h0[pix+8] = siluf_(fmaf(acc[mt][j][2], sc0, sh0));
            h1[pix+8] = siluf_(fmaf(acc[mt][j][3], sc1, sh1));
        }
    }
}

// ---------------------------------------------------------------- k23: fused dw3x3+BN+SiLU -> min proto distance -> per-image min/max
__global__ __launch_bounds__(256) void k23_dwdist(const float* __restrict__ dw,
                                                  const float* __restrict__ bn,
                                                  const float* __restrict__ protos){
    __shared__ float tile[32][10][34];
    __shared__ float ps[KK][PP];
    __shared__ float pn[KK];
    __shared__ float sdw[PP][9];
    __shared__ float ssc[PP], ssh[PP];
    __shared__ float smin[8], smax[8];

    int b   = blockIdx.z;
    int gx0 = blockIdx.x*32, gy0 = blockIdx.y*8;
    int tx  = threadIdx.x,  ty  = threadIdx.y;
    int tid = ty*32 + tx;

    for (int i = tid; i < KK*PP; i += 256) ps[i>>6][i&63] = protos[i];
    for (int i = tid; i < PP*9;  i += 256) sdw[i/9][i%9] = dw[i];
    if (tid < PP){
        float g=bn[tid], be=bn[PP+tid], m=bn[2*PP+tid], v=bn[3*PP+tid];
        float sc = g*rsqrtf(v+BN_EPS);
        ssc[tid] = sc; ssh[tid] = be - m*sc;
    }
    if (tid < KK){
        float s = 0.f;
        #pragma unroll
        for (int c=0;c<PP;c++){ float p = protos[tid*PP+c]; s = fmaf(p,p,s); }
        pn[tid] = s;
    }

    const float* hb = g_h + (size_t)b*PP*HWSZ;
    float nf = 0.f, dot[KK];
    #pragma unroll
    for (int k=0;k<KK;k++) dot[k] = 0.f;

    for (int c0 = 0; c0 < PP; c0 += 32){
        __syncthreads();
        for (int i = tid; i < 32*340; i += 256){
            int c   = i / 340;
            int rem = i - c*340;
            int r   = rem / 34;
            int col = rem - r*34;
            int yy = gy0 - 1 + r, xx = gx0 - 1 + col;
            float v = 0.f;
            if ((unsigned)yy < HH && (unsigned)xx < WW)
                v = hb[(size_t)(c0+c)*HWSZ + yy*WW + xx];
            tile[c][r][col] = v;
        }
        __syncthreads();
        #pragma unroll 4
        for (int c = 0; c < 32; c++){
            int cc = c0 + c;
            float s = 0.f;
            #pragma unroll
            for (int dy=0;dy<3;dy++)
                #pragma unroll
                for (int dx=0;dx<3;dx++)
                    s = fmaf(sdw[cc][dy*3+dx], tile[c][ty+dy][tx+dx], s);
            float pr = siluf_(fmaf(s, ssc[cc], ssh[cc]));
            nf = fmaf(pr, pr, nf);
            #pragma unroll
            for (int k=0;k<KK;k++) dot[k] = fmaf(pr, ps[k][cc], dot[k]);
        }
    }

    float m = 3.4e38f;
    #pragma unroll
    for (int k=0;k<KK;k++) m = fminf(m, nf + pn[k] - 2.f*dot[k]);
    float md = sqrtf(fmaxf(m, 0.f)) * (1.0f/(1.0f + 1e-6f));
    g_mind[b*HWSZ + (gy0+ty)*WW + gx0+tx] = md;

    float wmin = md, wmax = md;
    #pragma unroll
    for (int o=16;o>0;o>>=1){
        wmin = fminf(wmin, __shfl_xor_sync(0xffffffffu, wmin, o));
        wmax = fmaxf(wmax, __shfl_xor_sync(0xffffffffu, wmax, o));
    }
    int wd = tid >> 5, ld = tid & 31;
    if (ld == 0){ smin[wd] = wmin; smax[wd] = wmax; }
    __syncthreads();
    if (tid == 0){
        float bm = smin[0], bM = smax[0];
        #pragma unroll
        for (int i=1;i<8;i++){ bm = fminf(bm, smin[i]); bM = fmaxf(bM, smax[i]); }
        atomicMin(&g_minbits[b], __float_as_uint(bm));
        atomicMax(&g_maxbits[b], __float_as_uint(bM));
    }
}

// ---------------------------------------------------------------- k4: deviation -> two DS-conv branches -> fuse -> sigmoid -> factor
__global__ __launch_bounds__(256) void k4_attn(
        const float* __restrict__ bs_dw, const float* __restrict__ bs_bn1,
        const float* __restrict__ bs_pw, const float* __restrict__ bs_bn2,
        const float* __restrict__ bl_dw, const float* __restrict__ bl_bn1,
        const float* __restrict__ bl_pw, const float* __restrict__ bl_bn2,
        const float* __restrict__ fuse_w, const float* __restrict__ fuse_b,
        const float* __restrict__ gamma){
    __shared__ float sdev[12][36];
    int b   = blockIdx.z;
    int gx0 = blockIdx.x*32, gy0 = blockIdx.y*8;
    int tx  = threadIdx.x,  ty  = threadIdx.y;
    int tid = ty*32 + tx;

    float dmin = __uint_as_float(g_minbits[b]);
    float dmax = __uint_as_float(g_maxbits[b]);
    float inv  = 1.0f/(dmax - dmin + 1e-6f);
    const float* mdp = g_mind + b*HWSZ;

    for (int i = tid; i < 12*36; i += 256){
        int ly = i/36, lx = i%36;
        int yy = gy0 - 2 + ly, xx = gx0 - 2 + lx;
        float v = 0.f;
        if ((unsigned)yy < HH && (unsigned)xx < WW)
            v = (mdp[yy*WW + xx] - dmin) * inv;
        sdev[ly][lx] = v;
    }
    __syncthreads();

    int cy = ty + 2, cx = tx + 2;
    float t1 = 0.f;
    #pragma unroll
    for (int dy=0;dy<3;dy++)
        #pragma unroll
        for (int dx=0;dx<3;dx++)
            t1 = fmaf(bs_dw[dy*3+dx], sdev[cy+dy-1][cx+dx-1], t1);
    { float g=bs_bn1[0], be=bs_bn1[1], m=bs_bn1[2], v=bs_bn1[3];
      float sc = g*rsqrtf(v+BN_EPS); t1 = siluf_(fmaf(t1, sc, be - m*sc)); }
    float t2 = 0.f;
    #pragma unroll
    for (int dy=0;dy<5;dy++)
        #pragma unroll
        for (int dx=0;dx<5;dx++)
            t2 = fmaf(bl_dw[dy*5+dx], sdev[cy+dy-2][cx+dx-2], t2);
    { float g=bl_bn1[0], be=bl_bn1[1], m=bl_bn1[2], v=bl_bn1[3];
      float sc = g*rsqrtf(v+BN_EPS); t2 = siluf_(fmaf(t2, sc, be - m*sc)); }

    float logit = fuse_b[0];
    #pragma unroll
    for (int c=0;c<8;c++){
        float g=bs_bn2[c], be=bs_bn2[8+c], m=bs_bn2[16+c], v=bs_bn2[24+c];
        float sc = g*rsqrtf(v+BN_EPS);
        float f1 = siluf_(fmaf(bs_pw[c]*t1, sc, be - m*sc));
        logit = fmaf(fuse_w[c], f1, logit);
    }
    #pragma unroll
    for (int c=0;c<8;c++){
        float g=bl_bn2[c], be=bl_bn2[8+c], m=bl_bn2[16+c], v=bl_bn2[24+c];
        float sc = g*rsqrtf(v+BN_EPS);
        float f2 = siluf_(fmaf(bl_pw[c]*t2, sc, be - m*sc));
        logit = fmaf(fuse_w[8+c], f2, logit);
    }
    int gy = gy0 + ty, gx = gx0 + tx;
    g_factor[b*HWSZ + gy*WW + gx] = 1.0f + gamma[0]*sigmoidf_(logit);
}

// ---------------------------------------------------------------- k5: out = x * factor (broadcast over channels), pure streaming
__global__ __launch_bounds__(256) void k5_apply(const float* __restrict__ x,
                                                float* __restrict__ out){
    size_t i = ((size_t)blockIdx.x*256 + threadIdx.x) * 4;
    float4 xv = *(const float4*)(x + i);
    size_t pos = i & (size_t)(HWSZ - 1);
    int b      = (int)(i >> 22);
    float4 fv = *(const float4*)(g_factor + (size_t)b*HWSZ + pos);
    float4 ov;
    ov.x = xv.x * fv.x;
    ov.y = xv.y * fv.y;
    ov.z = xv.z * fv.z;
    ov.w = xv.w * fv.w;
    *(float4*)(out + i) = ov;
}

// ---------------------------------------------------------------- launch
extern "C" void kernel_launch(void* const* d_in, const int* in_sizes, int n_in,
                              void* d_out, int out_size){
    const float* x      = (const float*)d_in[0];
    const float* fp_w1  = (const float*)d_in[1];
    const float* fp_bn1 = (const float*)d_in[2];
    const float* fp_dw  = (const float*)d_in[3];
    const float* fp_bn2 = (const float*)d_in[4];
    const float* protos = (const float*)d_in[5];
    const float* bs_dw  = (const float*)d_in[6];
    const float* bs_bn1 = (const float*)d_in[7];
    const float* bs_pw  = (const float*)d_in[8];
    const float* bs_bn2 = (const float*)d_in[9];
    const float* bl_dw  = (const float*)d_in[10];
    const float* bl_bn1 = (const float*)d_in[11];
    const float* bl_pw  = (const float*)d_in[12];
    const float* bl_bn2 = (const float*)d_in[13];
    const float* fuse_w = (const float*)d_in[14];
    const float* fuse_b = (const float*)d_in[15];
    const float* gamma  = (const float*)d_in[16];
    float* out = (float*)d_out;

    cudaFuncSetAttribute(k1_mma, cudaFuncAttributeMaxDynamicSharedMemorySize, SM_TOTAL);
    k1_mma<<<dim3(128, BB), 256, SM_TOTAL>>>(x, fp_w1, fp_bn1);
    k23_dwdist<<<dim3(4, 16, BB), dim3(32, 8)>>>(fp_dw, fp_bn2, protos);
    k4_attn<<<dim3(4, 16, BB), dim3(32, 8)>>>(bs_dw, bs_bn1, bs_pw, bs_bn2,
                                              bl_dw, bl_bn1, bl_pw, bl_bn2,
                                              fuse_w, fuse_b, gamma);
    k5_apply<<<(BB*CIN*HWSZ)/4/256, 256>>>(x, out);
}

// round 7
// speedup vs baseline: 2.8209x; 1.1846x over previous
#include <cuda_runtime.h>
#include <cstdint>
#include <math.h>

#define BB 4
#define CIN 256
#define PP 64
#define HH 128
#define WW 128
#define HWSZ (HH*WW)
#define KK 8
#define BN_EPS 1e-5f

// Scratch (device globals: allocation-free)
__device__ float g_h[BB*PP*HWSZ];      // after 1x1 conv + BN + SiLU
__device__ float g_mind[BB*HWSZ];      // per-pixel min distance / (tau+1e-6)
__device__ float g_factor[BB*HWSZ];    // 1 + gamma*attn
__device__ unsigned int g_minbits[BB];
__device__ unsigned int g_maxbits[BB];

__device__ __forceinline__ float sigmoidf_(float x){ return 1.0f/(1.0f+__expf(-x)); }
__device__ __forceinline__ float siluf_(float x){ return x*sigmoidf_(x); }

__device__ __forceinline__ uint32_t smem_u32(const void* p){
    uint32_t a;
    asm("{ .reg .u64 t; cvta.to.shared.u64 t, %1; cvt.u32.u64 %0, t; }" : "=r"(a) : "l"(p));
    return a;
}
// pack two floats -> bf16x2 (low 16 = x0, high 16 = x1)
__device__ __forceinline__ uint32_t pack_bf16x2(float x0, float x1){
    uint32_t r;
    asm("cvt.rn.bf16x2.f32 %0, %1, %2;" : "=r"(r) : "f"(x1), "f"(x0));
    return r;
}
__device__ __forceinline__ void ldsm_x4(uint32_t* r, uint32_t addr){
    asm volatile("ldmatrix.sync.aligned.m8n8.x4.shared.b16 {%0,%1,%2,%3}, [%4];"
        : "=r"(r[0]),"=r"(r[1]),"=r"(r[2]),"=r"(r[3]) : "r"(addr));
}
__device__ __forceinline__ void ldsm_x2(uint32_t& r0, uint32_t& r1, uint32_t addr){
    asm volatile("ldmatrix.sync.aligned.m8n8.x2.shared.b16 {%0,%1}, [%2];"
        : "=r"(r0),"=r"(r1) : "r"(addr));
}
__device__ __forceinline__ void mma_bf16(float* d, const uint32_t* a, uint32_t b0, uint32_t b1){
    asm volatile("mma.sync.aligned.m16n8k16.row.col.f32.bf16.bf16.f32 "
        "{%0,%1,%2,%3},{%4,%5,%6,%7},{%8,%9},{%0,%1,%2,%3};"
        : "+f"(d[0]),"+f"(d[1]),"+f"(d[2]),"+f"(d[3])
        : "r"(a[0]),"r"(a[1]),"r"(a[2]),"r"(a[3]),"r"(b0),"r"(b1));
}

// ---------------- k1 SMEM layout (dynamic, byte offsets) ----------------
#define APITCH 36                        // u32 pitch (144B: 16B-aligned, bank-spread)
#define SM_SC    0                       // ssc[64]
#define SM_SH    256                     // ssh[64]
#define SM_AHI   512                     // 128 x APITCH u32
#define SM_BHI   (SM_AHI + 128*APITCH*4)
#define SM_TOTAL (SM_BHI + 64*APITCH*4)  // 28160 B

// ---------------------------------------------------------------- k1: 1x1 conv (GEMM 128pix x 64cout x 256K per CTA)
// bf16 HMMA single-term (error budget analysis: output rel err ~1e-4 << 1e-3).
__global__ __launch_bounds__(256)
void k1_mma(const float* __restrict__ x, const float* __restrict__ w,
            const float* __restrict__ bn){
    extern __shared__ char smem[];
    uint32_t sb = smem_u32(smem);
    float* ssc = (float*)(smem + SM_SC);
    float* ssh = (float*)(smem + SM_SH);
    uint32_t* a_hi = (uint32_t*)(smem + SM_AHI);
    uint32_t* b_hi = (uint32_t*)(smem + SM_BHI);

    int b    = blockIdx.y;
    int pix0 = blockIdx.x * 128;
    int tid  = threadIdx.x;
    int wid  = tid >> 5;
    int lane = tid & 31;
    int gid  = lane >> 2, tig = lane & 3;
    int pw   = (wid >> 1) * 32;          // warp pixel base (M32)
    int n0w  = (wid & 1) * 32;           // warp cout base (N32)
    const float* xb = x + (size_t)b*CIN*HWSZ + pix0;

    if (blockIdx.x == 0 && blockIdx.y == 0 && tid < BB){
        g_minbits[tid] = 0x7F7FFFFFu; g_maxbits[tid] = 0u;
    }
    if (tid < PP){
        float g = bn[tid], be = bn[PP+tid], m = bn[2*PP+tid], v = bn[3*PP+tid];
        float sc = g * rsqrtf(v + BN_EPS);
        ssc[tid] = sc; ssh[tid] = be - m*sc;
    }

    float acc[2][4][4];
    #pragma unroll
    for (int mt=0;mt<2;mt++)
        #pragma unroll
        for (int j=0;j<4;j++)
            #pragma unroll
            for (int i=0;i<4;i++) acc[mt][j][i] = 0.f;

    // ldmatrix source addresses (byte): A x4, B x2
    uint32_t a_row = (uint32_t)(lane & 15);
    uint32_t a_kof = (uint32_t)(lane >> 4) * 16;     // bytes (4 u32)
    uint32_t b_row = (uint32_t)(lane & 7);
    uint32_t b_kof = (uint32_t)((lane >> 3) & 1) * 16;

    #pragma unroll 1
    for (int c = 0; c < 4; c++){
        int k0 = c * 64;
        // ---- convert A: 128 px x 32 kpairs -> bf16x2, STS.128 ----
        #pragma unroll
        for (int it = 0; it < 4; it++){
            int i  = tid + it*256;       // 0..1023
            int px = i & 127;
            int kg = i >> 7;             // 0..7 (4 kpairs each)
            const float* xp = xb + px;
            uint32_t hi[4];
            #pragma unroll
            for (int t=0;t<4;t++){
                int kp = kg*4 + t;
                float x0 = xp[(size_t)(k0+2*kp  )*HWSZ];
                float x1 = xp[(size_t)(k0+2*kp+1)*HWSZ];
                hi[t] = pack_bf16x2(x0, x1);
            }
            *(uint4*)(a_hi + px*APITCH + kg*4) = make_uint4(hi[0],hi[1],hi[2],hi[3]);
        }
        // ---- convert B: 64 couts x 32 kpairs ----
        #pragma unroll
        for (int it = 0; it < 2; it++){
            int i  = tid + it*256;       // 0..511
            int co = i >> 3;
            int kg = i & 7;
            const float* wp = w + co*CIN + k0 + kg*8;
            float4 w0 = *(const float4*)wp;
            float4 w1 = *(const float4*)(wp + 4);
            uint32_t hi[4];
            hi[0] = pack_bf16x2(w0.x, w0.y);
            hi[1] = pack_bf16x2(w0.z, w0.w);
            hi[2] = pack_bf16x2(w1.x, w1.y);
            hi[3] = pack_bf16x2(w1.z, w1.w);
            *(uint4*)(b_hi + co*APITCH + kg*4) = make_uint4(hi[0],hi[1],hi[2],hi[3]);
        }
        __syncthreads();

        // ---- MMA: 4 k16 steps ----
        #pragma unroll
        for (int ks = 0; ks < 4; ks++){
            uint32_t kbyte = (uint32_t)ks * 32;      // ks*8 u32
            uint32_t ah[2][4];
            #pragma unroll
            for (int mt=0;mt<2;mt++){
                uint32_t ra = (pw + mt*16 + a_row) * (APITCH*4) + kbyte + a_kof;
                ldsm_x4(ah[mt], sb + SM_AHI + ra);
            }
            #pragma unroll
            for (int j=0;j<4;j++){
                uint32_t rb = (n0w + j*8 + b_row) * (APITCH*4) + kbyte + b_kof;
                uint32_t bh0, bh1;
                ldsm_x2(bh0, bh1, sb + SM_BHI + rb);
                #pragma unroll
                for (int mt=0;mt<2;mt++)
                    mma_bf16(acc[mt][j], ah[mt], bh0, bh1);
            }
        }
        __syncthreads();
    }

    // ---- epilogue: BN + SiLU, store ----
    #pragma unroll
    for (int mt=0;mt<2;mt++){
        int pix = pix0 + pw + mt*16 + gid;
        #pragma unroll
        for (int j=0;j<4;j++){
            int cc = n0w + j*8 + tig*2;
            float sc0 = ssc[cc],   sh0 = ssh[cc];
            float sc1 = ssc[cc+1], sh1 = ssh[cc+1];
            float* h0 = g_h + (size_t)(b*PP + cc)*HWSZ;
            float* h1 = h0 + HWSZ;
            h0[pix]   = siluf_(fmaf(acc[mt][j][0], sc0, sh0));
            h1[pix]   = siluf_(fmaf(acc[mt][j][1], sc1, sh1));
            h0[pix+8] = siluf_(fmaf(acc[mt][j][2], sc0, sh0));
            h1[pix+8] = siluf_(fmaf(acc[mt][j][3], sc1, sh1));
        }
    }
}

// ---------------------------------------------------------------- k23: fused dw3x3+BN+SiLU -> min proto distance -> per-image min/max
__global__ __launch_bounds__(256) void k23_dwdist(const float* __restrict__ dw,
                                                  const float* __restrict__ bn,
                                                  const float* __restrict__ protos){
    __shared__ float tile[32][10][34];
    __shared__ float ps[KK][PP];
    __shared__ float pn[KK];
    __shared__ float sdw[PP][9];
    __shared__ float ssc[PP], ssh[PP];
    __shared__ float smin[8], smax[8];

    int b   = blockIdx.z;
    int gx0 = blockIdx.x*32, gy0 = blockIdx.y*8;
    int tx  = threadIdx.x,  ty  = threadIdx.y;
    int tid = ty*32 + tx;

    for (int i = tid; i < KK*PP; i += 256) ps[i>>6][i&63] = protos[i];
    for (int i = tid; i < PP*9;  i += 256) sdw[i/9][i%9] = dw[i];
    if (tid < PP){
        float g=bn[tid], be=bn[PP+tid], m=bn[2*PP+tid], v=bn[3*PP+tid];
        float sc = g*rsqrtf(v+BN_EPS);
        ssc[tid] = sc; ssh[tid] = be - m*sc;
    }
    if (tid < KK){
        float s = 0.f;
        #pragma unroll
        for (int c=0;c<PP;c++){ float p = protos[tid*PP+c]; s = fmaf(p,p,s); }
        pn[tid] = s;
    }

    const float* hb = g_h + (size_t)b*PP*HWSZ;
    float nf = 0.f, dot[KK];
    #pragma unroll
    for (int k=0;k<KK;k++) dot[k] = 0.f;

    for (int c0 = 0; c0 < PP; c0 += 32){
        __syncthreads();
        for (int i = tid; i < 32*340; i += 256){
            int c   = i / 340;
            int rem = i - c*340;
            int r   = rem / 34;
            int col = rem - r*34;
            int yy = gy0 - 1 + r, xx = gx0 - 1 + col;
            float v = 0.f;
            if ((unsigned)yy < HH && (unsigned)xx < WW)
                v = hb[(size_t)(c0+c)*HWSZ + yy*WW + xx];
            tile[c][r][col] = v;
        }
        __syncthreads();
        #pragma unroll 4
        for (int c = 0; c < 32; c++){
            int cc = c0 + c;
            float s = 0.f;
            #pragma unroll
            for (int dy=0;dy<3;dy++)
                #pragma unroll
                for (int dx=0;dx<3;dx++)
                    s = fmaf(sdw[cc][dy*3+dx], tile[c][ty+dy][tx+dx], s);
            float pr = siluf_(fmaf(s, ssc[cc], ssh[cc]));
            nf = fmaf(pr, pr, nf);
            #pragma unroll
            for (int k=0;k<KK;k++) dot[k] = fmaf(pr, ps[k][cc], dot[k]);
        }
    }

    float m = 3.4e38f;
    #pragma unroll
    for (int k=0;k<KK;k++) m = fminf(m, nf + pn[k] - 2.f*dot[k]);
    float md = sqrtf(fmaxf(m, 0.f)) * (1.0f/(1.0f + 1e-6f));
    g_mind[b*HWSZ + (gy0+ty)*WW + gx0+tx] = md;

    float wmin = md, wmax = md;
    #pragma unroll
    for (int o=16;o>0;o>>=1){
        wmin = fminf(wmin, __shfl_xor_sync(0xffffffffu, wmin, o));
        wmax = fmaxf(wmax, __shfl_xor_sync(0xffffffffu, wmax, o));
    }
    int wd = tid >> 5, ld = tid & 31;
    if (ld == 0){ smin[wd] = wmin; smax[wd] = wmax; }
    __syncthreads();
    if (tid == 0){
        float bm = smin[0], bM = smax[0];
        #pragma unroll
        for (int i=1;i<8;i++){ bm = fminf(bm, smin[i]); bM = fmaxf(bM, smax[i]); }
        atomicMin(&g_minbits[b], __float_as_uint(bm));
        atomicMax(&g_maxbits[b], __float_as_uint(bM));
    }
}

// ---------------------------------------------------------------- k4: deviation -> two DS-conv branches -> fuse -> sigmoid -> factor
__global__ __launch_bounds__(256) void k4_attn(
        const float* __restrict__ bs_dw, const float* __restrict__ bs_bn1,
        const float* __restrict__ bs_pw, const float* __restrict__ bs_bn2,
        const float* __restrict__ bl_dw, const float* __restrict__ bl_bn1,
        const float* __restrict__ bl_pw, const float* __restrict__ bl_bn2,
        const float* __restrict__ fuse_w, const float* __restrict__ fuse_b,
        const float* __restrict__ gamma){
    __shared__ float sdev[12][36];
    int b   = blockIdx.z;
    int gx0 = blockIdx.x*32, gy0 = blockIdx.y*8;
    int tx  = threadIdx.x,  ty  = threadIdx.y;
    int tid = ty*32 + tx;

    float dmin = __uint_as_float(g_minbits[b]);
    float dmax = __uint_as_float(g_maxbits[b]);
    float inv  = 1.0f/(dmax - dmin + 1e-6f);
    const float* mdp = g_mind + b*HWSZ;

    for (int i = tid; i < 12*36; i += 256){
        int ly = i/36, lx = i%36;
        int yy = gy0 - 2 + ly, xx = gx0 - 2 + lx;
        float v = 0.f;
        if ((unsigned)yy < HH && (unsigned)xx < WW)
            v = (mdp[yy*WW + xx] - dmin) * inv;
        sdev[ly][lx] = v;
    }
    __syncthreads();

    int cy = ty + 2, cx = tx + 2;
    float t1 = 0.f;
    #pragma unroll
    for (int dy=0;dy<3;dy++)
        #pragma unroll
        for (int dx=0;dx<3;dx++)
            t1 = fmaf(bs_dw[dy*3+dx], sdev[cy+dy-1][cx+dx-1], t1);
    { float g=bs_bn1[0], be=bs_bn1[1], m=bs_bn1[2], v=bs_bn1[3];
      float sc = g*rsqrtf(v+BN_EPS); t1 = siluf_(fmaf(t1, sc, be - m*sc)); }
    float t2 = 0.f;
    #pragma unroll
    for (int dy=0;dy<5;dy++)
        #pragma unroll
        for (int dx=0;dx<5;dx++)
            t2 = fmaf(bl_dw[dy*5+dx], sdev[cy+dy-2][cx+dx-2], t2);
    { float g=bl_bn1[0], be=bl_bn1[1], m=bl_bn1[2], v=bl_bn1[3];
      float sc = g*rsqrtf(v+BN_EPS); t2 = siluf_(fmaf(t2, sc, be - m*sc)); }

    float logit = fuse_b[0];
    #pragma unroll
    for (int c=0;c<8;c++){
        float g=bs_bn2[c], be=bs_bn2[8+c], m=bs_bn2[16+c], v=bs_bn2[24+c];
        float sc = g*rsqrtf(v+BN_EPS);
        float f1 = siluf_(fmaf(bs_pw[c]*t1, sc, be - m*sc));
        logit = fmaf(fuse_w[c], f1, logit);
    }
    #pragma unroll
    for (int c=0;c<8;c++){
        float g=bl_bn2[c], be=bl_bn2[8+c], m=bl_bn2[16+c], v=bl_bn2[24+c];
        float sc = g*rsqrtf(v+BN_EPS);
        float f2 = siluf_(fmaf(bl_pw[c]*t2, sc, be - m*sc));
        logit = fmaf(fuse_w[8+c], f2, logit);
    }
    int gy = gy0 + ty, gx = gx0 + tx;
    g_factor[b*HWSZ + gy*WW + gx] = 1.0f + gamma[0]*sigmoidf_(logit);
}

// ---------------------------------------------------------------- k5: out = x * factor (broadcast over channels), pure streaming
__global__ __launch_bounds__(256) void k5_apply(const float* __restrict__ x,
                                                float* __restrict__ out){
    size_t i = ((size_t)blockIdx.x*256 + threadIdx.x) * 4;
    float4 xv = *(const float4*)(x + i);
    size_t pos = i & (size_t)(HWSZ - 1);
    int b      = (int)(i >> 22);
    float4 fv = *(const float4*)(g_factor + (size_t)b*HWSZ + pos);
    float4 ov;
    ov.x = xv.x * fv.x;
    ov.y = xv.y * fv.y;
    ov.z = xv.z * fv.z;
    ov.w = xv.w * fv.w;
    *(float4*)(out + i) = ov;
}

// ---------------------------------------------------------------- launch
extern "C" void kernel_launch(void* const* d_in, const int* in_sizes, int n_in,
                              void* d_out, int out_size){
    const float* x      = (const float*)d_in[0];
    const float* fp_w1  = (const float*)d_in[1];
    const float* fp_bn1 = (const float*)d_in[2];
    const float* fp_dw  = (const float*)d_in[3];
    const float* fp_bn2 = (const float*)d_in[4];
    const float* protos = (const float*)d_in[5];
    const float* bs_dw  = (const float*)d_in[6];
    const float* bs_bn1 = (const float*)d_in[7];
    const float* bs_pw  = (const float*)d_in[8];
    const float* bs_bn2 = (const float*)d_in[9];
    const float* bl_dw  = (const float*)d_in[10];
    const float* bl_bn1 = (const float*)d_in[11];
    const float* bl_pw  = (const float*)d_in[12];
    const float* bl_bn2 = (const float*)d_in[13];
    const float* fuse_w = (const float*)d_in[14];
    const float* fuse_b = (const float*)d_in[15];
    const float* gamma  = (const float*)d_in[16];
    float* out = (float*)d_out;

    cudaFuncSetAttribute(k1_mma, cudaFuncAttributeMaxDynamicSharedMemorySize, SM_TOTAL);
    k1_mma<<<dim3(128, BB), 256, SM_TOTAL>>>(x, fp_w1, fp_bn1);
    k23_dwdist<<<dim3(4, 16, BB), dim3(32, 8)>>>(fp_dw, fp_bn2, protos);
    k4_attn<<<dim3(4, 16, BB), dim3(32, 8)>>>(bs_dw, bs_bn1, bs_pw, bs_bn2,
                                              bl_dw, bl_bn1, bl_pw, bl_bn2,
                                              fuse_w, fuse_b, gamma);
    k5_apply<<<(BB*CIN*HWSZ)/4/256, 256>>>(x, out);
}

// round 8
// speedup vs baseline: 2.9520x; 1.0465x over previous
#include <cuda_runtime.h>
#include <cstdint>
#include <math.h>

#define BB 4
#define CIN 256
#define PP 64
#define HH 128
#define WW 128
#define HWSZ (HH*WW)
#define KK 8
#define BN_EPS 1e-5f
#define NCTA234 (4*16*BB)

// Scratch (device globals: allocation-free)
__device__ float g_h[BB*PP*HWSZ];      // after 1x1 conv + BN + SiLU
__device__ float g_mind[BB*HWSZ];      // per-pixel min distance / (tau+1e-6)
__device__ float g_factor[BB*HWSZ];    // 1 + gamma*attn
__device__ unsigned int g_minbits[BB];
__device__ unsigned int g_maxbits[BB];
__device__ unsigned int g_bar;

__device__ __forceinline__ float sigmoidf_(float x){ return 1.0f/(1.0f+__expf(-x)); }
__device__ __forceinline__ float siluf_(float x){ return x*sigmoidf_(x); }

__device__ __forceinline__ uint32_t smem_u32(const void* p){
    uint32_t a;
    asm("{ .reg .u64 t; cvta.to.shared.u64 t, %1; cvt.u32.u64 %0, t; }" : "=r"(a) : "l"(p));
    return a;
}
// pack two floats -> bf16x2 (low 16 = x0, high 16 = x1)
__device__ __forceinline__ uint32_t pack_bf16x2(float x0, float x1){
    uint32_t r;
    asm("cvt.rn.bf16x2.f32 %0, %1, %2;" : "=r"(r) : "f"(x1), "f"(x0));
    return r;
}
__device__ __forceinline__ void ldsm_x4(uint32_t* r, uint32_t addr){
    asm volatile("ldmatrix.sync.aligned.m8n8.x4.shared.b16 {%0,%1,%2,%3}, [%4];"
        : "=r"(r[0]),"=r"(r[1]),"=r"(r[2]),"=r"(r[3]) : "r"(addr));
}
__device__ __forceinline__ void ldsm_x2(uint32_t& r0, uint32_t& r1, uint32_t addr){
    asm volatile("ldmatrix.sync.aligned.m8n8.x2.shared.b16 {%0,%1}, [%2];"
        : "=r"(r0),"=r"(r1) : "r"(addr));
}
__device__ __forceinline__ void mma_bf16(float* d, const uint32_t* a, uint32_t b0, uint32_t b1){
    asm volatile("mma.sync.aligned.m16n8k16.row.col.f32.bf16.bf16.f32 "
        "{%0,%1,%2,%3},{%4,%5,%6,%7},{%8,%9},{%0,%1,%2,%3};"
        : "+f"(d[0]),"+f"(d[1]),"+f"(d[2]),"+f"(d[3])
        : "r"(a[0]),"r"(a[1]),"r"(a[2]),"r"(a[3]),"r"(b0),"r"(b1));
}
__device__ __forceinline__ uint32_t ldcg_u32(const unsigned int* p){
    uint32_t v;
    asm volatile("ld.global.cg.u32 %0, [%1];" : "=r"(v) : "l"(p));
    return v;
}

// ---------------- k1 SMEM layout: double-buffered ----------------
#define APITCH 36                        // u32 pitch (144B: 16B-aligned, bank-spread)
#define SM_SC    0                       // ssc[64]
#define SM_SH    256                     // ssh[64]
#define ABYTES   (128*APITCH*4)          // 18432
#define BBYTES   (64*APITCH*4)           // 9216
#define BUFBYTES (ABYTES + BBYTES)       // 27648
#define SM_A0    512
#define SM_B0    (SM_A0 + ABYTES)
#define SM_TOTAL (SM_A0 + 2*BUFBYTES)    // 55808

// convert one K=64 chunk of A (x) and B (w) into a buffer
static __device__ __forceinline__ void conv_chunk(const float* __restrict__ xb,
                                                  const float* __restrict__ w,
                                                  int k0, char* smem, int bufoff, int tid){
    uint32_t* a_buf = (uint32_t*)(smem + SM_A0 + bufoff);
    uint32_t* b_buf = (uint32_t*)(smem + SM_B0 + bufoff);
    #pragma unroll
    for (int it = 0; it < 4; it++){
        int i  = tid + it*256;       // 0..1023
        int px = i & 127;
        int kg = i >> 7;             // 0..7 (4 kpairs each)
        const float* xp = xb + px;
        uint32_t hi[4];
        #pragma unroll
        for (int t=0;t<4;t++){
            int kp = kg*4 + t;
            float x0 = xp[(size_t)(k0+2*kp  )*HWSZ];
            float x1 = xp[(size_t)(k0+2*kp+1)*HWSZ];
            hi[t] = pack_bf16x2(x0, x1);
        }
        *(uint4*)(a_buf + px*APITCH + kg*4) = make_uint4(hi[0],hi[1],hi[2],hi[3]);
    }
    #pragma unroll
    for (int it = 0; it < 2; it++){
        int i  = tid + it*256;       // 0..511
        int co = i >> 3;
        int kg = i & 7;
        const float* wp = w + co*CIN + k0 + kg*8;
        float4 w0 = *(const float4*)wp;
        float4 w1 = *(const float4*)(wp + 4);
        uint32_t hi[4];
        hi[0] = pack_bf16x2(w0.x, w0.y);
        hi[1] = pack_bf16x2(w0.z, w0.w);
        hi[2] = pack_bf16x2(w1.x, w1.y);
        hi[3] = pack_bf16x2(w1.z, w1.w);
        *(uint4*)(b_buf + co*APITCH + kg*4) = make_uint4(hi[0],hi[1],hi[2],hi[3]);
    }
}

// ---------------------------------------------------------------- k1: 1x1 conv, bf16 HMMA, double-buffered
__global__ __launch_bounds__(256)
void k1_mma(const float* __restrict__ x, const float* __restrict__ w,
            const float* __restrict__ bn){
    extern __shared__ char smem[];
    uint32_t sb = smem_u32(smem);
    float* ssc = (float*)(smem + SM_SC);
    float* ssh = (float*)(smem + SM_SH);

    int b    = blockIdx.y;
    int pix0 = blockIdx.x * 128;
    int tid  = threadIdx.x;
    int wid  = tid >> 5;
    int lane = tid & 31;
    int gid  = lane >> 2, tig = lane & 3;
    int pw   = (wid >> 1) * 32;          // warp pixel base (M32)
    int n0w  = (wid & 1) * 32;           // warp cout base (N32)
    const float* xb = x + (size_t)b*CIN*HWSZ + pix0;

    if (blockIdx.x == 0 && blockIdx.y == 0 && tid < BB + 1){
        if (tid < BB){ g_minbits[tid] = 0x7F7FFFFFu; g_maxbits[tid] = 0u; }
        else g_bar = 0u;
    }
    if (tid < PP){
        float g = bn[tid], be = bn[PP+tid], m = bn[2*PP+tid], v = bn[3*PP+tid];
        float sc = g * rsqrtf(v + BN_EPS);
        ssc[tid] = sc; ssh[tid] = be - m*sc;
    }

    float acc[2][4][4];
    #pragma unroll
    for (int mt=0;mt<2;mt++)
        #pragma unroll
        for (int j=0;j<4;j++)
            #pragma unroll
            for (int i=0;i<4;i++) acc[mt][j][i] = 0.f;

    // ldmatrix source addresses
    uint32_t a_row = (uint32_t)(lane & 15);
    uint32_t a_kof = (uint32_t)(lane >> 4) * 16;
    uint32_t b_row = (uint32_t)(lane & 7);
    uint32_t b_kof = (uint32_t)((lane >> 3) & 1) * 16;

    conv_chunk(xb, w, 0, smem, 0, tid);
    __syncthreads();

    #pragma unroll 1
    for (int c = 0; c < 4; c++){
        int curoff = (c & 1) * BUFBYTES;
        // stage next chunk into the other buffer (overlaps with MMA below)
        if (c < 3)
            conv_chunk(xb, w, (c+1)*64, smem, (~c & 1) * BUFBYTES, tid);

        // MMA on current buffer: 4 k16 steps
        #pragma unroll
        for (int ks = 0; ks < 4; ks++){
            uint32_t kbyte = (uint32_t)ks * 32;
            uint32_t ah[2][4];
            #pragma unroll
            for (int mt=0;mt<2;mt++){
                uint32_t ra = (pw + mt*16 + a_row) * (APITCH*4) + kbyte + a_kof;
                ldsm_x4(ah[mt], sb + SM_A0 + curoff + ra);
            }
            #pragma unroll
            for (int j=0;j<4;j++){
                uint32_t rb = (n0w + j*8 + b_row) * (APITCH*4) + kbyte + b_kof;
                uint32_t bh0, bh1;
                ldsm_x2(bh0, bh1, sb + SM_B0 + curoff + rb);
                #pragma unroll
                for (int mt=0;mt<2;mt++)
                    mma_bf16(acc[mt][j], ah[mt], bh0, bh1);
            }
        }
        __syncthreads();
    }

    // ---- epilogue: BN + SiLU, store ----
    #pragma unroll
    for (int mt=0;mt<2;mt++){
        int pix = pix0 + pw + mt*16 + gid;
        #pragma unroll
        for (int j=0;j<4;j++){
            int cc = n0w + j*8 + tig*2;
            float sc0 = ssc[cc],   sh0 = ssh[cc];
            float sc1 = ssc[cc+1], sh1 = ssh[cc+1];
            float* h0 = g_h + (size_t)(b*PP + cc)*HWSZ;
            float* h1 = h0 + HWSZ;
            h0[pix]   = siluf_(fmaf(acc[mt][j][0], sc0, sh0));
            h1[pix]   = siluf_(fmaf(acc[mt][j][1], sc1, sh1));
            h0[pix+8] = siluf_(fmaf(acc[mt][j][2], sc0, sh0));
            h1[pix+8] = siluf_(fmaf(acc[mt][j][3], sc1, sh1));
        }
    }
}

// ---------------------------------------------------------------- k234: dw3x3+BN+SiLU -> min dist -> grid barrier -> attention -> factor
__global__ __launch_bounds__(256) void k234(
        const float* __restrict__ dw, const float* __restrict__ bn,
        const float* __restrict__ protos,
        const float* __restrict__ bs_dw, const float* __restrict__ bs_bn1,
        const float* __restrict__ bs_pw, const float* __restrict__ bs_bn2,
        const float* __restrict__ bl_dw, const float* __restrict__ bl_bn1,
        const float* __restrict__ bl_pw, const float* __restrict__ bl_bn2,
        const float* __restrict__ fuse_w, const float* __restrict__ fuse_b,
        const float* __restrict__ gamma){
    __shared__ float tile[32][10][34];
    __shared__ float ps[KK][PP];
    __shared__ float pn[KK];
    __shared__ float sdw[PP][9];
    __shared__ float ssc[PP], ssh[PP];
    __shared__ float smin[8], smax[8];
    __shared__ float sdev[12][36];
    __shared__ float sminmax[2];

    int b   = blockIdx.z;
    int gx0 = blockIdx.x*32, gy0 = blockIdx.y*8;
    int tx  = threadIdx.x,  ty  = threadIdx.y;
    int tid = ty*32 + tx;

    for (int i = tid; i < KK*PP; i += 256) ps[i>>6][i&63] = protos[i];
    for (int i = tid; i < PP*9;  i += 256) sdw[i/9][i%9] = dw[i];
    if (tid < PP){
        float g=bn[tid], be=bn[PP+tid], m=bn[2*PP+tid], v=bn[3*PP+tid];
        float sc = g*rsqrtf(v+BN_EPS);
        ssc[tid] = sc; ssh[tid] = be - m*sc;
    }
    if (tid < KK){
        float s = 0.f;
        #pragma unroll
        for (int c=0;c<PP;c++){ float p = protos[tid*PP+c]; s = fmaf(p,p,s); }
        pn[tid] = s;
    }

    const float* hb = g_h + (size_t)b*PP*HWSZ;
    float nf = 0.f, dot[KK];
    #pragma unroll
    for (int k=0;k<KK;k++) dot[k] = 0.f;

    for (int c0 = 0; c0 < PP; c0 += 32){
        __syncthreads();
        for (int i = tid; i < 32*340; i += 256){
            int c   = i / 340;
            int rem = i - c*340;
            int r   = rem / 34;
            int col = rem - r*34;
            int yy = gy0 - 1 + r, xx = gx0 - 1 + col;
            float v = 0.f;
            if ((unsigned)yy < HH && (unsigned)xx < WW)
                v = hb[(size_t)(c0+c)*HWSZ + yy*WW + xx];
            tile[c][r][col] = v;
        }
        __syncthreads();
        #pragma unroll 4
        for (int c = 0; c < 32; c++){
            int cc = c0 + c;
            float s = 0.f;
            #pragma unroll
            for (int dy=0;dy<3;dy++)
                #pragma unroll
                for (int dx=0;dx<3;dx++)
                    s = fmaf(sdw[cc][dy*3+dx], tile[c][ty+dy][tx+dx], s);
            float pr = siluf_(fmaf(s, ssc[cc], ssh[cc]));
            nf = fmaf(pr, pr, nf);
            #pragma unroll
            for (int k=0;k<KK;k++) dot[k] = fmaf(pr, ps[k][cc], dot[k]);
        }
    }

    float m = 3.4e38f;
    #pragma unroll
    for (int k=0;k<KK;k++) m = fminf(m, nf + pn[k] - 2.f*dot[k]);
    float md = sqrtf(fmaxf(m, 0.f)) * (1.0f/(1.0f + 1e-6f));
    g_mind[b*HWSZ + (gy0+ty)*WW + gx0+tx] = md;

    float wmin = md, wmax = md;
    #pragma unroll
    for (int o=16;o>0;o>>=1){
        wmin = fminf(wmin, __shfl_xor_sync(0xffffffffu, wmin, o));
        wmax = fmaxf(wmax, __shfl_xor_sync(0xffffffffu, wmax, o));
    }
    int wd = tid >> 5, ld = tid & 31;
    if (ld == 0){ smin[wd] = wmin; smax[wd] = wmax; }
    __syncthreads();

    // ---------- grid-wide barrier (all NCTA234 CTAs co-resident by occupancy) ----------
    if (tid == 0){
        float bm = smin[0], bM = smax[0];
        #pragma unroll
        for (int i=1;i<8;i++){ bm = fminf(bm, smin[i]); bM = fmaxf(bM, smax[i]); }
        atomicMin(&g_minbits[b], __float_as_uint(bm));
        atomicMax(&g_maxbits[b], __float_as_uint(bM));
        __threadfence();
        atomicAdd(&g_bar, 1u);
        while (ldcg_u32(&g_bar) < (unsigned)NCTA234) { }
        __threadfence();
        sminmax[0] = __uint_as_float(ldcg_u32(&g_minbits[b]));
        sminmax[1] = __uint_as_float(ldcg_u32(&g_maxbits[b]));
    }
    __syncthreads();

    // ---------- attention head (former k4) ----------
    float dmin = sminmax[0];
    float inv  = 1.0f/(sminmax[1] - dmin + 1e-6f);
    const float* mdp = g_mind + b*HWSZ;

    for (int i = tid; i < 12*36; i += 256){
        int ly = i/36, lx = i%36;
        int yy = gy0 - 2 + ly, xx = gx0 - 2 + lx;
        float v = 0.f;
        if ((unsigned)yy < HH && (unsigned)xx < WW)
            v = (mdp[yy*WW + xx] - dmin) * inv;
        sdev[ly][lx] = v;
    }
    __syncthreads();

    int cy = ty + 2, cx = tx + 2;
    float t1 = 0.f;
    #pragma unroll
    for (int dy=0;dy<3;dy++)
        #pragma unroll
        for (int dx=0;dx<3;dx++)
            t1 = fmaf(bs_dw[dy*3+dx], sdev[cy+dy-1][cx+dx-1], t1);
    { float g=bs_bn1[0], be=bs_bn1[1], mm=bs_bn1[2], v=bs_bn1[3];
      float sc = g*rsqrtf(v+BN_EPS); t1 = siluf_(fmaf(t1, sc, be - mm*sc)); }
    float t2 = 0.f;
    #pragma unroll
    for (int dy=0;dy<5;dy++)
        #pragma unroll
        for (int dx=0;dx<5;dx++)
            t2 = fmaf(bl_dw[dy*5+dx], sdev[cy+dy-2][cx+dx-2], t2);
    { float g=bl_bn1[0], be=bl_bn1[1], mm=bl_bn1[2], v=bl_bn1[3];
      float sc = g*rsqrtf(v+BN_EPS); t2 = siluf_(fmaf(t2, sc, be - mm*sc)); }

    float logit = fuse_b[0];
    #pragma unroll
    for (int c=0;c<8;c++){
        float g=bs_bn2[c], be=bs_bn2[8+c], mm=bs_bn2[16+c], v=bs_bn2[24+c];
        float sc = g*rsqrtf(v+BN_EPS);
        float f1 = siluf_(fmaf(bs_pw[c]*t1, sc, be - mm*sc));
        logit = fmaf(fuse_w[c], f1, logit);
    }
    #pragma unroll
    for (int c=0;c<8;c++){
        float g=bl_bn2[c], be=bl_bn2[8+c], mm=bl_bn2[16+c], v=bl_bn2[24+c];
        float sc = g*rsqrtf(v+BN_EPS);
        float f2 = siluf_(fmaf(bl_pw[c]*t2, sc, be - mm*sc));
        logit = fmaf(fuse_w[8+c], f2, logit);
    }
    g_factor[b*HWSZ + (gy0+ty)*WW + gx0+tx] = 1.0f + gamma[0]*sigmoidf_(logit);
}

// ---------------------------------------------------------------- k5: out = x * factor, pure streaming
__global__ __launch_bounds__(256) void k5_apply(const float* __restrict__ x,
                                                float* __restrict__ out){
    size_t i = ((size_t)blockIdx.x*256 + threadIdx.x) * 4;
    float4 xv = *(const float4*)(x + i);
    size_t pos = i & (size_t)(HWSZ - 1);
    int b      = (int)(i >> 22);
    float4 fv = *(const float4*)(g_factor + (size_t)b*HWSZ + pos);
    float4 ov;
    ov.x = xv.x * fv.x;
    ov.y = xv.y * fv.y;
    ov.z = xv.z * fv.z;
    ov.w = xv.w * fv.w;
    *(float4*)(out + i) = ov;
}

// ---------------------------------------------------------------- launch
extern "C" void kernel_launch(void* const* d_in, const int* in_sizes, int n_in,
                              void* d_out, int out_size){
    const float* x      = (const float*)d_in[0];
    const float* fp_w1  = (const float*)d_in[1];
    const float* fp_bn1 = (const float*)d_in[2];
    const float* fp_dw  = (const float*)d_in[3];
    const float* fp_bn2 = (const float*)d_in[4];
    const float* protos = (const float*)d_in[5];
    const float* bs_dw  = (const float*)d_in[6];
    const float* bs_bn1 = (const float*)d_in[7];
    const float* bs_pw  = (const float*)d_in[8];
    const float* bs_bn2 = (const float*)d_in[9];
    const float* bl_dw  = (const float*)d_in[10];
    const float* bl_bn1 = (const float*)d_in[11];
    const float* bl_pw  = (const float*)d_in[12];
    const float* bl_bn2 = (const float*)d_in[13];
    const float* fuse_w = (const float*)d_in[14];
    const float* fuse_b = (const float*)d_in[15];
    const float* gamma  = (const float*)d_in[16];
    float* out = (float*)d_out;

    cudaFuncSetAttribute(k1_mma, cudaFuncAttributeMaxDynamicSharedMemorySize, SM_TOTAL);
    k1_mma<<<dim3(128, BB), 256, SM_TOTAL>>>(x, fp_w1, fp_bn1);
    k234<<<dim3(4, 16, BB), dim3(32, 8)>>>(fp_dw, fp_bn2, protos,
                                           bs_dw, bs_bn1, bs_pw, bs_bn2,
                                           bl_dw, bl_bn1, bl_pw, bl_bn2,
                                           fuse_w, fuse_b, gamma);
    k5_apply<<<(BB*CIN*HWSZ)/4/256, 256>>>(x, out);
}

// round 9
// speedup vs baseline: 2.9600x; 1.0027x over previous
#include <cuda_runtime.h>
#include <cstdint>
#include <math.h>

#define BB 4
#define CIN 256
#define PP 64
#define HH 128
#define WW 128
#define HWSZ (HH*WW)
#define KK 8
#define BN_EPS 1e-5f
#define NCTA234 (4*16*BB)

// Scratch (device globals: allocation-free)
__device__ float g_h[BB*PP*HWSZ];      // after 1x1 conv + BN + SiLU
__device__ float g_mind[BB*HWSZ];      // per-pixel min distance / (tau+1e-6)
__device__ float g_factor[BB*HWSZ];    // 1 + gamma*attn
__device__ unsigned int g_minbits[BB];
__device__ unsigned int g_maxbits[BB];
__device__ unsigned int g_bar;

__device__ __forceinline__ float sigmoidf_(float x){ return 1.0f/(1.0f+__expf(-x)); }
__device__ __forceinline__ float siluf_(float x){ return x*sigmoidf_(x); }

__device__ __forceinline__ uint32_t smem_u32(const void* p){
    uint32_t a;
    asm("{ .reg .u64 t; cvta.to.shared.u64 t, %1; cvt.u32.u64 %0, t; }" : "=r"(a) : "l"(p));
    return a;
}
__device__ __forceinline__ uint32_t pack_bf16x2(float x0, float x1){
    uint32_t r;
    asm("cvt.rn.bf16x2.f32 %0, %1, %2;" : "=r"(r) : "f"(x1), "f"(x0));
    return r;
}
__device__ __forceinline__ void ldsm_x4(uint32_t* r, uint32_t addr){
    asm volatile("ldmatrix.sync.aligned.m8n8.x4.shared.b16 {%0,%1,%2,%3}, [%4];"
        : "=r"(r[0]),"=r"(r[1]),"=r"(r[2]),"=r"(r[3]) : "r"(addr));
}
__device__ __forceinline__ void ldsm_x2(uint32_t& r0, uint32_t& r1, uint32_t addr){
    asm volatile("ldmatrix.sync.aligned.m8n8.x2.shared.b16 {%0,%1}, [%2];"
        : "=r"(r0),"=r"(r1) : "r"(addr));
}
__device__ __forceinline__ void mma_bf16(float* d, const uint32_t* a, uint32_t b0, uint32_t b1){
    asm volatile("mma.sync.aligned.m16n8k16.row.col.f32.bf16.bf16.f32 "
        "{%0,%1,%2,%3},{%4,%5,%6,%7},{%8,%9},{%0,%1,%2,%3};"
        : "+f"(d[0]),"+f"(d[1]),"+f"(d[2]),"+f"(d[3])
        : "r"(a[0]),"r"(a[1]),"r"(a[2]),"r"(a[3]),"r"(b0),"r"(b1));
}
__device__ __forceinline__ uint32_t ldcg_u32(const unsigned int* p){
    uint32_t v;
    asm volatile("ld.global.cg.u32 %0, [%1];" : "=r"(v) : "l"(p));
    return v;
}
__device__ __forceinline__ void bar_arrive_release(unsigned int* p){
    uint32_t old;
    asm volatile("atom.global.release.gpu.add.u32 %0, [%1], 1;" : "=r"(old) : "l"(p) : "memory");
}
__device__ __forceinline__ uint32_t ld_acquire(const unsigned int* p){
    uint32_t v;
    asm volatile("ld.global.acquire.gpu.u32 %0, [%1];" : "=r"(v) : "l"(p) : "memory");
    return v;
}

// ---------------- k1 SMEM layout: double-buffered ----------------
#define APITCH 36
#define SM_SC    0
#define SM_SH    256
#define ABYTES   (128*APITCH*4)
#define BBYTES   (64*APITCH*4)
#define BUFBYTES (ABYTES + BBYTES)
#define SM_A0    512
#define SM_B0    (SM_A0 + ABYTES)
#define SM_TOTAL (SM_A0 + 2*BUFBYTES)    // 55808

static __device__ __forceinline__ void conv_chunk(const float* __restrict__ xb,
                                                  const float* __restrict__ w,
                                                  int k0, char* smem, int bufoff, int tid){
    uint32_t* a_buf = (uint32_t*)(smem + SM_A0 + bufoff);
    uint32_t* b_buf = (uint32_t*)(smem + SM_B0 + bufoff);
    #pragma unroll
    for (int it = 0; it < 4; it++){
        int i  = tid + it*256;
        int px = i & 127;
        int kg = i >> 7;
        const float* xp = xb + px;
        uint32_t hi[4];
        #pragma unroll
        for (int t=0;t<4;t++){
            int kp = kg*4 + t;
            float x0 = xp[(size_t)(k0+2*kp  )*HWSZ];
            float x1 = xp[(size_t)(k0+2*kp+1)*HWSZ];
            hi[t] = pack_bf16x2(x0, x1);
        }
        *(uint4*)(a_buf + px*APITCH + kg*4) = make_uint4(hi[0],hi[1],hi[2],hi[3]);
    }
    #pragma unroll
    for (int it = 0; it < 2; it++){
        int i  = tid + it*256;
        int co = i >> 3;
        int kg = i & 7;
        const float* wp = w + co*CIN + k0 + kg*8;
        float4 w0 = *(const float4*)wp;
        float4 w1 = *(const float4*)(wp + 4);
        uint32_t hi[4];
        hi[0] = pack_bf16x2(w0.x, w0.y);
        hi[1] = pack_bf16x2(w0.z, w0.w);
        hi[2] = pack_bf16x2(w1.x, w1.y);
        hi[3] = pack_bf16x2(w1.z, w1.w);
        *(uint4*)(b_buf + co*APITCH + kg*4) = make_uint4(hi[0],hi[1],hi[2],hi[3]);
    }
}

// ---------------------------------------------------------------- k1: 1x1 conv, bf16 HMMA, double-buffered, 4 CTAs/SM
__global__ __launch_bounds__(256, 4)
void k1_mma(const float* __restrict__ x, const float* __restrict__ w,
            const float* __restrict__ bn){
    extern __shared__ char smem[];
    uint32_t sb = smem_u32(smem);
    float* ssc = (float*)(smem + SM_SC);
    float* ssh = (float*)(smem + SM_SH);

    int b    = blockIdx.y;
    int pix0 = blockIdx.x * 128;
    int tid  = threadIdx.x;
    int wid  = tid >> 5;
    int lane = tid & 31;
    int gid  = lane >> 2, tig = lane & 3;
    int pw   = (wid >> 1) * 32;
    int n0w  = (wid & 1) * 32;
    const float* xb = x + (size_t)b*CIN*HWSZ + pix0;

    if (blockIdx.x == 0 && blockIdx.y == 0 && tid < BB + 1){
        if (tid < BB){ g_minbits[tid] = 0x7F7FFFFFu; g_maxbits[tid] = 0u; }
        else g_bar = 0u;
    }
    if (tid < PP){
        float g = bn[tid], be = bn[PP+tid], m = bn[2*PP+tid], v = bn[3*PP+tid];
        float sc = g * rsqrtf(v + BN_EPS);
        ssc[tid] = sc; ssh[tid] = be - m*sc;
    }

    float acc[2][4][4];
    #pragma unroll
    for (int mt=0;mt<2;mt++)
        #pragma unroll
        for (int j=0;j<4;j++)
            #pragma unroll
            for (int i=0;i<4;i++) acc[mt][j][i] = 0.f;

    uint32_t a_row = (uint32_t)(lane & 15);
    uint32_t a_kof = (uint32_t)(lane >> 4) * 16;
    uint32_t b_row = (uint32_t)(lane & 7);
    uint32_t b_kof = (uint32_t)((lane >> 3) & 1) * 16;

    conv_chunk(xb, w, 0, smem, 0, tid);
    __syncthreads();

    #pragma unroll 1
    for (int c = 0; c < 4; c++){
        int curoff = (c & 1) * BUFBYTES;
        if (c < 3)
            conv_chunk(xb, w, (c+1)*64, smem, (~c & 1) * BUFBYTES, tid);

        #pragma unroll
        for (int ks = 0; ks < 4; ks++){
            uint32_t kbyte = (uint32_t)ks * 32;
            uint32_t ah[2][4];
            #pragma unroll
            for (int mt=0;mt<2;mt++){
                uint32_t ra = (pw + mt*16 + a_row) * (APITCH*4) + kbyte + a_kof;
                ldsm_x4(ah[mt], sb + SM_A0 + curoff + ra);
            }
            #pragma unroll
            for (int j=0;j<4;j++){
                uint32_t rb = (n0w + j*8 + b_row) * (APITCH*4) + kbyte + b_kof;
                uint32_t bh0, bh1;
                ldsm_x2(bh0, bh1, sb + SM_B0 + curoff + rb);
                #pragma unroll
                for (int mt=0;mt<2;mt++)
                    mma_bf16(acc[mt][j], ah[mt], bh0, bh1);
            }
        }
        __syncthreads();
    }

    #pragma unroll
    for (int mt=0;mt<2;mt++){
        int pix = pix0 + pw + mt*16 + gid;
        #pragma unroll
        for (int j=0;j<4;j++){
            int cc = n0w + j*8 + tig*2;
            float sc0 = ssc[cc],   sh0 = ssh[cc];
            float sc1 = ssc[cc+1], sh1 = ssh[cc+1];
            float* h0 = g_h + (size_t)(b*PP + cc)*HWSZ;
            float* h1 = h0 + HWSZ;
            h0[pix]   = siluf_(fmaf(acc[mt][j][0], sc0, sh0));
            h1[pix]   = siluf_(fmaf(acc[mt][j][1], sc1, sh1));
            h0[pix+8] = siluf_(fmaf(acc[mt][j][2], sc0, sh0));
            h1[pix+8] = siluf_(fmaf(acc[mt][j][3], sc1, sh1));
        }
    }
}

// ---------------------------------------------------------------- k234: dw3x3+BN+SiLU -> min dist -> PROPER grid barrier -> attention
__global__ __launch_bounds__(256) void k234(
        const float* __restrict__ dw, const float* __restrict__ bn,
        const float* __restrict__ protos,
        const float* __restrict__ bs_dw, const float* __restrict__ bs_bn1,
        const float* __restrict__ bs_pw, const float* __restrict__ bs_bn2,
        const float* __restrict__ bl_dw, const float* __restrict__ bl_bn1,
        const float* __restrict__ bl_pw, const float* __restrict__ bl_bn2,
        const float* __restrict__ fuse_w, const float* __restrict__ fuse_b,
        const float* __restrict__ gamma){
    __shared__ float tile[32][10][34];
    __shared__ float ps[KK][PP];
    __shared__ float pn[KK];
    __shared__ float sdw[PP][9];
    __shared__ float ssc[PP], ssh[PP];
    __shared__ float smin[8], smax[8];
    __shared__ float sdev[12][36];
    __shared__ float sminmax[2];

    int b   = blockIdx.z;
    int gx0 = blockIdx.x*32, gy0 = blockIdx.y*8;
    int tx  = threadIdx.x,  ty  = threadIdx.y;
    int tid = ty*32 + tx;

    for (int i = tid; i < KK*PP; i += 256) ps[i>>6][i&63] = protos[i];
    for (int i = tid; i < PP*9;  i += 256) sdw[i/9][i%9] = dw[i];
    if (tid < PP){
        float g=bn[tid], be=bn[PP+tid], m=bn[2*PP+tid], v=bn[3*PP+tid];
        float sc = g*rsqrtf(v+BN_EPS);
        ssc[tid] = sc; ssh[tid] = be - m*sc;
    }
    if (tid < KK){
        float s = 0.f;
        #pragma unroll
        for (int c=0;c<PP;c++){ float p = protos[tid*PP+c]; s = fmaf(p,p,s); }
        pn[tid] = s;
    }

    const float* hb = g_h + (size_t)b*PP*HWSZ;
    float nf = 0.f, dot[KK];
    #pragma unroll
    for (int k=0;k<KK;k++) dot[k] = 0.f;

    for (int c0 = 0; c0 < PP; c0 += 32){
        __syncthreads();
        for (int i = tid; i < 32*340; i += 256){
            int c   = i / 340;
            int rem = i - c*340;
            int r   = rem / 34;
            int col = rem - r*34;
            int yy = gy0 - 1 + r, xx = gx0 - 1 + col;
            float v = 0.f;
            if ((unsigned)yy < HH && (unsigned)xx < WW)
                v = hb[(size_t)(c0+c)*HWSZ + yy*WW + xx];
            tile[c][r][col] = v;
        }
        __syncthreads();
        #pragma unroll 4
        for (int c = 0; c < 32; c++){
            int cc = c0 + c;
            float s = 0.f;
            #pragma unroll
            for (int dy=0;dy<3;dy++)
                #pragma unroll
                for (int dx=0;dx<3;dx++)
                    s = fmaf(sdw[cc][dy*3+dx], tile[c][ty+dy][tx+dx], s);
            float pr = siluf_(fmaf(s, ssc[cc], ssh[cc]));
            nf = fmaf(pr, pr, nf);
            #pragma unroll
            for (int k=0;k<KK;k++) dot[k] = fmaf(pr, ps[k][cc], dot[k]);
        }
    }

    float m = 3.4e38f;
    #pragma unroll
    for (int k=0;k<KK;k++) m = fminf(m, nf + pn[k] - 2.f*dot[k]);
    float md = sqrtf(fmaxf(m, 0.f)) * (1.0f/(1.0f + 1e-6f));
    g_mind[b*HWSZ + (gy0+ty)*WW + gx0+tx] = md;

    float wmin = md, wmax = md;
    #pragma unroll
    for (int o=16;o>0;o>>=1){
        wmin = fminf(wmin, __shfl_xor_sync(0xffffffffu, wmin, o));
        wmax = fmaxf(wmax, __shfl_xor_sync(0xffffffffu, wmax, o));
    }
    int wd = tid >> 5, ld = tid & 31;
    if (ld == 0){ smin[wd] = wmin; smax[wd] = wmax; }

    // EVERY thread fences its own g_mind store device-wide before the arrive.
    __threadfence();
    __syncthreads();

    // ---------- grid-wide barrier (release arrive / acquire spin) ----------
    if (tid == 0){
        float bm = smin[0], bM = smax[0];
        #pragma unroll
        for (int i=1;i<8;i++){ bm = fminf(bm, smin[i]); bM = fmaxf(bM, smax[i]); }
        atomicMin(&g_minbits[b], __float_as_uint(bm));
        atomicMax(&g_maxbits[b], __float_as_uint(bM));
        __threadfence();
        bar_arrive_release(&g_bar);
        while (ld_acquire(&g_bar) < (unsigned)NCTA234) { }
        sminmax[0] = __uint_as_float(ldcg_u32(&g_minbits[b]));
        sminmax[1] = __uint_as_float(ldcg_u32(&g_maxbits[b]));
    }
    __syncthreads();

    // ---------- attention head ----------
    float dmin = sminmax[0];
    float inv  = 1.0f/(sminmax[1] - dmin + 1e-6f);
    const float* mdp = g_mind + b*HWSZ;

    for (int i = tid; i < 12*36; i += 256){
        int ly = i/36, lx = i%36;
        int yy = gy0 - 2 + ly, xx = gx0 - 2 + lx;
        float v = 0.f;
        if ((unsigned)yy < HH && (unsigned)xx < WW)
            v = (mdp[yy*WW + xx] - dmin) * inv;
        sdev[ly][lx] = v;
    }
    __syncthreads();

    int cy = ty + 2, cx = tx + 2;
    float t1 = 0.f;
    #pragma unroll
    for (int dy=0;dy<3;dy++)
        #pragma unroll
        for (int dx=0;dx<3;dx++)
            t1 = fmaf(bs_dw[dy*3+dx], sdev[cy+dy-1][cx+dx-1], t1);
    { float g=bs_bn1[0], be=bs_bn1[1], mm=bs_bn1[2], v=bs_bn1[3];
      float sc = g*rsqrtf(v+BN_EPS); t1 = siluf_(fmaf(t1, sc, be - mm*sc)); }
    float t2 = 0.f;
    #pragma unroll
    for (int dy=0;dy<5;dy++)
        #pragma unroll
        for (int dx=0;dx<5;dx++)
            t2 = fmaf(bl_dw[dy*5+dx], sdev[cy+dy-2][cx+dx-2], t2);
    { float g=bl_bn1[0], be=bl_bn1[1], mm=bl_bn1[2], v=bl_bn1[3];
      float sc = g*rsqrtf(v+BN_EPS); t2 = siluf_(fmaf(t2, sc, be - mm*sc)); }

    float logit = fuse_b[0];
    #pragma unroll
    for (int c=0;c<8;c++){
        float g=bs_bn2[c], be=bs_bn2[8+c], mm=bs_bn2[16+c], v=bs_bn2[24+c];
        float sc = g*rsqrtf(v+BN_EPS);
        float f1 = siluf_(fmaf(bs_pw[c]*t1, sc, be - mm*sc));
        logit = fmaf(fuse_w[c], f1, logit);
    }
    #pragma unroll
    for (int c=0;c<8;c++){
        float g=bl_bn2[c], be=bl_bn2[8+c], mm=bl_bn2[16+c], v=bl_bn2[24+c];
        float sc = g*rsqrtf(v+BN_EPS);
        float f2 = siluf_(fmaf(bl_pw[c]*t2, sc, be - mm*sc));
        logit = fmaf(fuse_w[8+c], f2, logit);
    }
    g_factor[b*HWSZ + (gy0+ty)*WW + gx0+tx] = 1.0f + gamma[0]*sigmoidf_(logit);
}

// ---------------------------------------------------------------- k5: out = x * factor, pure streaming
__global__ __launch_bounds__(256) void k5_apply(const float* __restrict__ x,
                                                float* __restrict__ out){
    size_t i = ((size_t)blockIdx.x*256 + threadIdx.x) * 4;
    float4 xv = *(const float4*)(x + i);
    size_t pos = i & (size_t)(HWSZ - 1);
    int b      = (int)(i >> 22);
    float4 fv = *(const float4*)(g_factor + (size_t)b*HWSZ + pos);
    float4 ov;
    ov.x = xv.x * fv.x;
    ov.y = xv.y * fv.y;
    ov.z = xv.z * fv.z;
    ov.w = xv.w * fv.w;
    *(float4*)(out + i) = ov;
}

// ---------------------------------------------------------------- launch
extern "C" void kernel_launch(void* const* d_in, const int* in_sizes, int n_in,
                              void* d_out, int out_size){
    const float* x      = (const float*)d_in[0];
    const float* fp_w1  = (const float*)d_in[1];
    const float* fp_bn1 = (const float*)d_in[2];
    const float* fp_dw  = (const float*)d_in[3];
    const float* fp_bn2 = (const float*)d_in[4];
    const float* protos = (const float*)d_in[5];
    const float* bs_dw  = (const float*)d_in[6];
    const float* bs_bn1 = (const float*)d_in[7];
    const float* bs_pw  = (const float*)d_in[8];
    const float* bs_bn2 = (const float*)d_in[9];
    const float* bl_dw  = (const float*)d_in[10];
    const float* bl_bn1 = (const float*)d_in[11];
    const float* bl_pw  = (const float*)d_in[12];
    const float* bl_bn2 = (const float*)d_in[13];
    const float* fuse_w = (const float*)d_in[14];
    const float* fuse_b = (const float*)d_in[15];
    const float* gamma  = (const float*)d_in[16];
    float* out = (float*)d_out;

    cudaFuncSetAttribute(k1_mma, cudaFuncAttributeMaxDynamicSharedMemorySize, SM_TOTAL);
    k1_mma<<<dim3(128, BB), 256, SM_TOTAL>>>(x, fp_w1, fp_bn1);
    k234<<<dim3(4, 16, BB), dim3(32, 8)>>>(fp_dw, fp_bn2, protos,
                                           bs_dw, bs_bn1, bs_pw, bs_bn2,
                                           bl_dw, bl_bn1, bl_pw, bl_bn2,
                                           fuse_w, fuse_b, gamma);
    k5_apply<<<(BB*CIN*HWSZ)/4/256, 256>>>(x, out);
}

// round 10
// speedup vs baseline: 2.9739x; 1.0047x over previous
#include <cuda_runtime.h>
#include <cstdint>
#include <math.h>

#define BB 4
#define CIN 256
#define PP 64
#define HH 128
#define WW 128
#define HWSZ (HH*WW)
#define KK 8
#define BN_EPS 1e-5f
#define NCTA234 (4*16*BB)

// Scratch (device globals: allocation-free)
__device__ float g_h[BB*PP*HWSZ];      // after 1x1 conv + BN + SiLU
__device__ float g_mind[BB*HWSZ];      // per-pixel min distance / (tau+1e-6)
__device__ float g_factor[BB*HWSZ];    // 1 + gamma*attn
__device__ unsigned int g_minbits[BB];
__device__ unsigned int g_maxbits[BB];
__device__ unsigned int g_bar;

__device__ __forceinline__ float sigmoidf_(float x){ return 1.0f/(1.0f+__expf(-x)); }
__device__ __forceinline__ float siluf_(float x){ return x*sigmoidf_(x); }

__device__ __forceinline__ uint32_t smem_u32(const void* p){
    uint32_t a;
    asm("{ .reg .u64 t; cvta.to.shared.u64 t, %1; cvt.u32.u64 %0, t; }" : "=r"(a) : "l"(p));
    return a;
}
__device__ __forceinline__ uint32_t pack_bf16x2(float x0, float x1){
    uint32_t r;
    asm("cvt.rn.bf16x2.f32 %0, %1, %2;" : "=r"(r) : "f"(x1), "f"(x0));
    return r;
}
__device__ __forceinline__ void ldsm_x4(uint32_t* r, uint32_t addr){
    asm volatile("ldmatrix.sync.aligned.m8n8.x4.shared.b16 {%0,%1,%2,%3}, [%4];"
        : "=r"(r[0]),"=r"(r[1]),"=r"(r[2]),"=r"(r[3]) : "r"(addr));
}
__device__ __forceinline__ void ldsm_x2(uint32_t& r0, uint32_t& r1, uint32_t addr){
    asm volatile("ldmatrix.sync.aligned.m8n8.x2.shared.b16 {%0,%1}, [%2];"
        : "=r"(r0),"=r"(r1) : "r"(addr));
}
__device__ __forceinline__ void mma_bf16(float* d, const uint32_t* a, uint32_t b0, uint32_t b1){
    asm volatile("mma.sync.aligned.m16n8k16.row.col.f32.bf16.bf16.f32 "
        "{%0,%1,%2,%3},{%4,%5,%6,%7},{%8,%9},{%0,%1,%2,%3};"
        : "+f"(d[0]),"+f"(d[1]),"+f"(d[2]),"+f"(d[3])
        : "r"(a[0]),"r"(a[1]),"r"(a[2]),"r"(a[3]),"r"(b0),"r"(b1));
}
__device__ __forceinline__ uint32_t ldcg_u32(const unsigned int* p){
    uint32_t v;
    asm volatile("ld.global.cg.u32 %0, [%1];" : "=r"(v) : "l"(p));
    return v;
}
__device__ __forceinline__ void bar_arrive_release(unsigned int* p){
    uint32_t old;
    asm volatile("atom.global.release.gpu.add.u32 %0, [%1], 1;" : "=r"(old) : "l"(p) : "memory");
}
__device__ __forceinline__ uint32_t ld_acquire(const unsigned int* p){
    uint32_t v;
    asm volatile("ld.global.acquire.gpu.u32 %0, [%1];" : "=r"(v) : "l"(p) : "memory");
    return v;
}

// ---------------- k1 SMEM layout: double-buffered ----------------
#define APITCH 36
#define SM_SC    0
#define SM_SH    256
#define ABYTES   (128*APITCH*4)
#define BBYTES   (64*APITCH*4)
#define BUFBYTES (ABYTES + BBYTES)
#define SM_A0    512
#define SM_B0    (SM_A0 + ABYTES)
#define SM_TOTAL (SM_A0 + 2*BUFBYTES)    // 55808

static __device__ __forceinline__ void conv_chunk(const float* __restrict__ xb,
                                                  const float* __restrict__ w,
                                                  int k0, char* smem, int bufoff, int tid){
    uint32_t* a_buf = (uint32_t*)(smem + SM_A0 + bufoff);
    uint32_t* b_buf = (uint32_t*)(smem + SM_B0 + bufoff);
    #pragma unroll
    for (int it = 0; it < 4; it++){
        int i  = tid + it*256;
        int px = i & 127;
        int kg = i >> 7;
        const float* xp = xb + px;
        uint32_t hi[4];
        #pragma unroll
        for (int t=0;t<4;t++){
            int kp = kg*4 + t;
            float x0 = xp[(size_t)(k0+2*kp  )*HWSZ];
            float x1 = xp[(size_t)(k0+2*kp+1)*HWSZ];
            hi[t] = pack_bf16x2(x0, x1);
        }
        *(uint4*)(a_buf + px*APITCH + kg*4) = make_uint4(hi[0],hi[1],hi[2],hi[3]);
    }
    #pragma unroll
    for (int it = 0; it < 2; it++){
        int i  = tid + it*256;
        int co = i >> 3;
        int kg = i & 7;
        const float* wp = w + co*CIN + k0 + kg*8;
        float4 w0 = *(const float4*)wp;
        float4 w1 = *(const float4*)(wp + 4);
        uint32_t hi[4];
        hi[0] = pack_bf16x2(w0.x, w0.y);
        hi[1] = pack_bf16x2(w0.z, w0.w);
        hi[2] = pack_bf16x2(w1.x, w1.y);
        hi[3] = pack_bf16x2(w1.z, w1.w);
        *(uint4*)(b_buf + co*APITCH + kg*4) = make_uint4(hi[0],hi[1],hi[2],hi[3]);
    }
}

// ---------------------------------------------------------------- k1: 1x1 conv, bf16 HMMA, double-buffered, 4 CTAs/SM
__global__ __launch_bounds__(256, 4)
void k1_mma(const float* __restrict__ x, const float* __restrict__ w,
            const float* __restrict__ bn){
    extern __shared__ char smem[];
    uint32_t sb = smem_u32(smem);
    float* ssc = (float*)(smem + SM_SC);
    float* ssh = (float*)(smem + SM_SH);

    int b    = blockIdx.y;
    int pix0 = blockIdx.x * 128;
    int tid  = threadIdx.x;
    int wid  = tid >> 5;
    int lane = tid & 31;
    int gid  = lane >> 2, tig = lane & 3;
    int pw   = (wid >> 1) * 32;
    int n0w  = (wid & 1) * 32;
    const float* xb = x + (size_t)b*CIN*HWSZ + pix0;

    if (blockIdx.x == 0 && blockIdx.y == 0 && tid < BB + 1){
        if (tid < BB){ g_minbits[tid] = 0x7F7FFFFFu; g_maxbits[tid] = 0u; }
        else g_bar = 0u;
    }
    if (tid < PP){
        float g = bn[tid], be = bn[PP+tid], m = bn[2*PP+tid], v = bn[3*PP+tid];
        float sc = g * rsqrtf(v + BN_EPS);
        ssc[tid] = sc; ssh[tid] = be - m*sc;
    }

    float acc[2][4][4];
    #pragma unroll
    for (int mt=0;mt<2;mt++)
        #pragma unroll
        for (int j=0;j<4;j++)
            #pragma unroll
            for (int i=0;i<4;i++) acc[mt][j][i] = 0.f;

    uint32_t a_row = (uint32_t)(lane & 15);
    uint32_t a_kof = (uint32_t)(lane >> 4) * 16;
    uint32_t b_row = (uint32_t)(lane & 7);
    uint32_t b_kof = (uint32_t)((lane >> 3) & 1) * 16;

    conv_chunk(xb, w, 0, smem, 0, tid);
    __syncthreads();

    #pragma unroll 1
    for (int c = 0; c < 4; c++){
        int curoff = (c & 1) * BUFBYTES;
        if (c < 3)
            conv_chunk(xb, w, (c+1)*64, smem, (~c & 1) * BUFBYTES, tid);

        #pragma unroll
        for (int ks = 0; ks < 4; ks++){
            uint32_t kbyte = (uint32_t)ks * 32;
            uint32_t ah[2][4];
            #pragma unroll
            for (int mt=0;mt<2;mt++){
                uint32_t ra = (pw + mt*16 + a_row) * (APITCH*4) + kbyte + a_kof;
                ldsm_x4(ah[mt], sb + SM_A0 + curoff + ra);
            }
            #pragma unroll
            for (int j=0;j<4;j++){
                uint32_t rb = (n0w + j*8 + b_row) * (APITCH*4) + kbyte + b_kof;
                uint32_t bh0, bh1;
                ldsm_x2(bh0, bh1, sb + SM_B0 + curoff + rb);
                #pragma unroll
                for (int mt=0;mt<2;mt++)
                    mma_bf16(acc[mt][j], ah[mt], bh0, bh1);
            }
        }
        __syncthreads();
    }

    #pragma unroll
    for (int mt=0;mt<2;mt++){
        int pix = pix0 + pw + mt*16 + gid;
        #pragma unroll
        for (int j=0;j<4;j++){
            int cc = n0w + j*8 + tig*2;
            float sc0 = ssc[cc],   sh0 = ssh[cc];
            float sc1 = ssc[cc+1], sh1 = ssh[cc+1];
            float* h0 = g_h + (size_t)(b*PP + cc)*HWSZ;
            float* h1 = h0 + HWSZ;
            h0[pix]   = siluf_(fmaf(acc[mt][j][0], sc0, sh0));
            h1[pix]   = siluf_(fmaf(acc[mt][j][1], sc1, sh1));
            h0[pix+8] = siluf_(fmaf(acc[mt][j][2], sc0, sh0));
            h1[pix+8] = siluf_(fmaf(acc[mt][j][3], sc1, sh1));
        }
    }
}

// ---------------- k234 dynamic smem layout (float offsets) ----------------
// tile   [64][10][34] : 0      .. 21760
// ps     [8][64]      : 21760
// sdw    [64][9]      : 22272
// ssc    [64]         : 22848
// ssh    [64]         : 22912
// pn     [8]          : 22976
// smin   [8]          : 22984
// smax   [8]          : 22992
// sdev   [12][36]     : 23000
// sminmax[2]          : 23432
#define K234_FLOATS 23440
#define K234_SMEM   (K234_FLOATS*4)

// ---------------------------------------------------------------- k234: single-pass dw3x3+dist -> grid barrier -> attention
__global__ __launch_bounds__(256) void k234(
        const float* __restrict__ dw, const float* __restrict__ bn,
        const float* __restrict__ protos,
        const float* __restrict__ bs_dw, const float* __restrict__ bs_bn1,
        const float* __restrict__ bs_pw, const float* __restrict__ bs_bn2,
        const float* __restrict__ bl_dw, const float* __restrict__ bl_bn1,
        const float* __restrict__ bl_pw, const float* __restrict__ bl_bn2,
        const float* __restrict__ fuse_w, const float* __restrict__ fuse_b,
        const float* __restrict__ gamma){
    extern __shared__ float sm[];
    float* tile = sm;                 // [c][r][col] = c*340 + r*34 + col
    float* ps   = sm + 21760;         // [k][c] = k*64 + c
    float* sdw  = sm + 22272;         // [c][j] = c*9 + j
    float* ssc  = sm + 22848;
    float* ssh  = sm + 22912;
    float* pn   = sm + 22976;
    float* smin = sm + 22984;
    float* smax = sm + 22992;
    float* sdev = sm + 23000;         // [ly][lx] = ly*36 + lx
    float* sminmax = sm + 23432;

    int b   = blockIdx.z;
    int gx0 = blockIdx.x*32, gy0 = blockIdx.y*8;
    int tx  = threadIdx.x,  ty  = threadIdx.y;
    int tid = ty*32 + tx;

    for (int i = tid; i < KK*PP; i += 256) ps[i] = protos[i];
    for (int i = tid; i < PP*9;  i += 256) sdw[i] = dw[i];
    if (tid < PP){
        float g=bn[tid], be=bn[PP+tid], m=bn[2*PP+tid], v=bn[3*PP+tid];
        float sc = g*rsqrtf(v+BN_EPS);
        ssc[tid] = sc; ssh[tid] = be - m*sc;
    }
    if (tid < KK){
        float s = 0.f;
        #pragma unroll
        for (int c=0;c<PP;c++){ float p = protos[tid*PP+c]; s = fmaf(p,p,s); }
        pn[tid] = s;
    }

    // ---- single-pass halo tile load: all 64 channels, 85 independent loads/thread ----
    const float* hb = g_h + (size_t)b*PP*HWSZ;
    for (int i = tid; i < 64*340; i += 256){
        int c   = i / 340;
        int rem = i - c*340;
        int r   = rem / 34;
        int col = rem - r*34;
        int yy = gy0 - 1 + r, xx = gx0 - 1 + col;
        float v = 0.f;
        if ((unsigned)yy < HH && (unsigned)xx < WW)
            v = hb[(size_t)c*HWSZ + yy*WW + xx];
        tile[i] = v;
    }
    __syncthreads();

    float nf = 0.f, dot[KK];
    #pragma unroll
    for (int k=0;k<KK;k++) dot[k] = 0.f;

    #pragma unroll 4
    for (int c = 0; c < PP; c++){
        const float* tc = tile + c*340 + ty*34 + tx;
        float s = 0.f;
        #pragma unroll
        for (int dy=0;dy<3;dy++)
            #pragma unroll
            for (int dx=0;dx<3;dx++)
                s = fmaf(sdw[c*9+dy*3+dx], tc[dy*34+dx], s);
        float pr = siluf_(fmaf(s, ssc[c], ssh[c]));
        nf = fmaf(pr, pr, nf);
        #pragma unroll
        for (int k=0;k<KK;k++) dot[k] = fmaf(pr, ps[k*PP+c], dot[k]);
    }

    float m = 3.4e38f;
    #pragma unroll
    for (int k=0;k<KK;k++) m = fminf(m, nf + pn[k] - 2.f*dot[k]);
    float md = sqrtf(fmaxf(m, 0.f)) * (1.0f/(1.0f + 1e-6f));
    g_mind[b*HWSZ + (gy0+ty)*WW + gx0+tx] = md;

    float wmin = md, wmax = md;
    #pragma unroll
    for (int o=16;o>0;o>>=1){
        wmin = fminf(wmin, __shfl_xor_sync(0xffffffffu, wmin, o));
        wmax = fmaxf(wmax, __shfl_xor_sync(0xffffffffu, wmax, o));
    }
    int wd = tid >> 5, ld = tid & 31;
    if (ld == 0){ smin[wd] = wmin; smax[wd] = wmax; }

    // EVERY thread fences its own g_mind store device-wide before the arrive.
    __threadfence();
    __syncthreads();

    // ---------- grid-wide barrier (release arrive / acquire spin) ----------
    if (tid == 0){
        float bm = smin[0], bM = smax[0];
        #pragma unroll
        for (int i=1;i<8;i++){ bm = fminf(bm, smin[i]); bM = fmaxf(bM, smax[i]); }
        atomicMin(&g_minbits[b], __float_as_uint(bm));
        atomicMax(&g_maxbits[b], __float_as_uint(bM));
        __threadfence();
        bar_arrive_release(&g_bar);
        while (ld_acquire(&g_bar) < (unsigned)NCTA234) { }
        sminmax[0] = __uint_as_float(ldcg_u32(&g_minbits[b]));
        sminmax[1] = __uint_as_float(ldcg_u32(&g_maxbits[b]));
    }
    __syncthreads();

    // ---------- attention head ----------
    float dmin = sminmax[0];
    float inv  = 1.0f/(sminmax[1] - dmin + 1e-6f);
    const float* mdp = g_mind + b*HWSZ;

    for (int i = tid; i < 12*36; i += 256){
        int ly = i/36, lx = i%36;
        int yy = gy0 - 2 + ly, xx = gx0 - 2 + lx;
        float v = 0.f;
        if ((unsigned)yy < HH && (unsigned)xx < WW)
            v = (mdp[yy*WW + xx] - dmin) * inv;
        sdev[i] = v;
    }
    __syncthreads();

    int cy = ty + 2, cx = tx + 2;
    float t1 = 0.f;
    #pragma unroll
    for (int dy=0;dy<3;dy++)
        #pragma unroll
        for (int dx=0;dx<3;dx++)
            t1 = fmaf(bs_dw[dy*3+dx], sdev[(cy+dy-1)*36 + cx+dx-1], t1);
    { float g=bs_bn1[0], be=bs_bn1[1], mm=bs_bn1[2], v=bs_bn1[3];
      float sc = g*rsqrtf(v+BN_EPS); t1 = siluf_(fmaf(t1, sc, be - mm*sc)); }
    float t2 = 0.f;
    #pragma unroll
    for (int dy=0;dy<5;dy++)
        #pragma unroll
        for (int dx=0;dx<5;dx++)
            t2 = fmaf(bl_dw[dy*5+dx], sdev[(cy+dy-2)*36 + cx+dx-2], t2);
    { float g=bl_bn1[0], be=bl_bn1[1], mm=bl_bn1[2], v=bl_bn1[3];
      float sc = g*rsqrtf(v+BN_EPS); t2 = siluf_(fmaf(t2, sc, be - mm*sc)); }

    float logit = fuse_b[0];
    #pragma unroll
    for (int c=0;c<8;c++){
        float g=bs_bn2[c], be=bs_bn2[8+c], mm=bs_bn2[16+c], v=bs_bn2[24+c];
        float sc = g*rsqrtf(v+BN_EPS);
        float f1 = siluf_(fmaf(bs_pw[c]*t1, sc, be - mm*sc));
        logit = fmaf(fuse_w[c], f1, logit);
    }
    #pragma unroll
    for (int c=0;c<8;c++){
        float g=bl_bn2[c], be=bl_bn2[8+c], mm=bl_bn2[16+c], v=bl_bn2[24+c];
        float sc = g*rsqrtf(v+BN_EPS);
        float f2 = siluf_(fmaf(bl_pw[c]*t2, sc, be - mm*sc));
        logit = fmaf(fuse_w[8+c], f2, logit);
    }
    g_factor[b*HWSZ + (gy0+ty)*WW + gx0+tx] = 1.0f + gamma[0]*sigmoidf_(logit);
}

// ---------------------------------------------------------------- k5: out = x * factor, 8 floats/thread for MLP
__global__ __launch_bounds__(256) void k5_apply(const float* __restrict__ x,
                                                float* __restrict__ out){
    size_t i = ((size_t)blockIdx.x*256 + threadIdx.x) * 8;   // 8-float slab, never crosses HWSZ
    float4 x0 = *(const float4*)(x + i);
    float4 x1 = *(const float4*)(x + i + 4);
    size_t pos = i & (size_t)(HWSZ - 1);
    int b      = (int)(i >> 22);
    const float* fb = g_factor + (size_t)b*HWSZ + pos;
    float4 f0 = *(const float4*)fb;
    float4 f1 = *(const float4*)(fb + 4);
    float4 o0, o1;
    o0.x = x0.x*f0.x; o0.y = x0.y*f0.y; o0.z = x0.z*f0.z; o0.w = x0.w*f0.w;
    o1.x = x1.x*f1.x; o1.y = x1.y*f1.y; o1.z = x1.z*f1.z; o1.w = x1.w*f1.w;
    *(float4*)(out + i)     = o0;
    *(float4*)(out + i + 4) = o1;
}

// ---------------------------------------------------------------- launch
extern "C" void kernel_launch(void* const* d_in, const int* in_sizes, int n_in,
                              void* d_out, int out_size){
    const float* x      = (const float*)d_in[0];
    const float* fp_w1  = (const float*)d_in[1];
    const float* fp_bn1 = (const float*)d_in[2];
    const float* fp_dw  = (const float*)d_in[3];
    const float* fp_bn2 = (const float*)d_in[4];
    const float* protos = (const float*)d_in[5];
    const float* bs_dw  = (const float*)d_in[6];
    const float* bs_bn1 = (const float*)d_in[7];
    const float* bs_pw  = (const float*)d_in[8];
    const float* bs_bn2 = (const float*)d_in[9];
    const float* bl_dw  = (const float*)d_in[10];
    const float* bl_bn1 = (const float*)d_in[11];
    const float* bl_pw  = (const float*)d_in[12];
    const float* bl_bn2 = (const float*)d_in[13];
    const float* fuse_w = (const float*)d_in[14];
    const float* fuse_b = (const float*)d_in[15];
    const float* gamma  = (const float*)d_in[16];
    float* out = (float*)d_out;

    cudaFuncSetAttribute(k1_mma, cudaFuncAttributeMaxDynamicSharedMemorySize, SM_TOTAL);
    cudaFuncSetAttribute(k234,   cudaFuncAttributeMaxDynamicSharedMemorySize, K234_SMEM);
    k1_mma<<<dim3(128, BB), 256, SM_TOTAL>>>(x, fp_w1, fp_bn1);
    k234<<<dim3(4, 16, BB), dim3(32, 8), K234_SMEM>>>(fp_dw, fp_bn2, protos,
                                           bs_dw, bs_bn1, bs_pw, bs_bn2,
                                           bl_dw, bl_bn1, bl_pw, bl_bn2,
                                           fuse_w, fuse_b, gamma);
    k5_apply<<<(BB*CIN*HWSZ)/8/256, 256>>>(x, out);
}